// round 2
// baseline (speedup 1.0000x reference)
#include <cuda_runtime.h>

#define S_LEN  2048
#define BATCH  2
#define HID    1024
#define NHEAD  16
#define DHEAD  64
#define MHEADS 32            // BATCH * NHEAD
#define K_DIM  1024
#define N_DIM  3072
#define M_DIM  4096          // S_LEN * BATCH

// Scratch (allocation-free rule: __device__ globals). 48 MB total.
__device__ float g_Q[(size_t)MHEADS * S_LEN * DHEAD];
__device__ float g_K[(size_t)MHEADS * S_LEN * DHEAD];
__device__ float g_V[(size_t)MHEADS * S_LEN * DHEAD];

// ---------------------------------------------------------------------------
// Kernel 1: QKV projection C[m][n] = sum_k A[m][k]*W[n][k] + bias[n],
// scattered directly into per-head Q/K/V layout [mh][s][d].
// Block tile 128x128, K-chunk 16, 256 threads, 8x8 per thread.
// ---------------------------------------------------------------------------
__global__ __launch_bounds__(256) void qkv_gemm_kernel(
    const float* __restrict__ A,      // [4096][1024] (s*B+b major)
    const float* __restrict__ W,      // [3072][1024]
    const float* __restrict__ bias)   // [3072]
{
    __shared__ float As[16][128];     // As[k][m]
    __shared__ float Bs[16][128];     // Bs[k][n]

    const int tid = threadIdx.x;
    const int tx  = tid & 15;         // n-tile index
    const int ty  = tid >> 4;         // m-tile index
    const int m0  = blockIdx.y * 128;
    const int n0  = blockIdx.x * 128;

    float acc[8][8];
    #pragma unroll
    for (int i = 0; i < 8; ++i)
        #pragma unroll
        for (int j = 0; j < 8; ++j) acc[i][j] = 0.f;

    const int lr = tid >> 2;          // 0..63 row
    const int lk = (tid & 3) << 2;    // 0,4,8,12 k-offset

    for (int k0 = 0; k0 < K_DIM; k0 += 16) {
        #pragma unroll
        for (int p = 0; p < 2; ++p) {
            int row = lr + p * 64;
            float4 va = *(const float4*)(A + (size_t)(m0 + row) * K_DIM + k0 + lk);
            As[lk + 0][row] = va.x; As[lk + 1][row] = va.y;
            As[lk + 2][row] = va.z; As[lk + 3][row] = va.w;
            float4 vb = *(const float4*)(W + (size_t)(n0 + row) * K_DIM + k0 + lk);
            Bs[lk + 0][row] = vb.x; Bs[lk + 1][row] = vb.y;
            Bs[lk + 2][row] = vb.z; Bs[lk + 3][row] = vb.w;
        }
        __syncthreads();

        #pragma unroll
        for (int k = 0; k < 16; ++k) {
            float a[8], b[8];
            *(float4*)&a[0] = *(const float4*)&As[k][ty * 8];
            *(float4*)&a[4] = *(const float4*)&As[k][ty * 8 + 4];
            *(float4*)&b[0] = *(const float4*)&Bs[k][tx * 8];
            *(float4*)&b[4] = *(const float4*)&Bs[k][tx * 8 + 4];
            #pragma unroll
            for (int i = 0; i < 8; ++i)
                #pragma unroll
                for (int j = 0; j < 8; ++j)
                    acc[i][j] = fmaf(a[i], b[j], acc[i][j]);
        }
        __syncthreads();
    }

    // Epilogue: bias + scatter into [mh = b*16+head][s][d] for q/k/v.
    #pragma unroll
    for (int j = 0; j < 8; ++j) {
        int n    = n0 + tx * 8 + j;
        float bj = bias[n];
        int head = n / 192;
        int w    = n - head * 192;      // 0..191
        int sel  = w >> 6;              // 0=q 1=k 2=v
        int d    = w & 63;
        float* dst = (sel == 0) ? g_Q : ((sel == 1) ? g_K : g_V);
        #pragma unroll
        for (int i = 0; i < 8; ++i) {
            int m  = m0 + ty * 8 + i;   // = s*BATCH + b
            int s  = m >> 1;
            int b  = m & 1;
            int mh = (b << 4) + head;
            dst[((size_t)mh * S_LEN + s) * DHEAD + d] = acc[i][j] + bj;
        }
    }
}

// ---------------------------------------------------------------------------
// Kernel 2: attention. One block = (head m, 64-row Q tile). Loops over 32
// K/V tiles of 64 rows. Per tile: S = (sq+sk-2 QK^T)*(-1/16) -> write scores
// -> P = exp(S) -> ctx += P @ V. 256 threads, 4x4 microtiles.
// ---------------------------------------------------------------------------
__global__ __launch_bounds__(256) void attn_kernel(
    float* __restrict__ ctx_out,      // [S][B][H]
    float* __restrict__ score_out)    // [MHEADS][S][S]
{
    extern __shared__ float smem[];
    float* Qt = smem;                 // [64][68]  Qt[d][i]
    float* Kt = smem + 64 * 68;       // [64][68]  Kt[d][j]
    float* Vs = smem + 2 * 64 * 68;   // [64][68]  Vs[j][d]
    float* Pt = smem + 3 * 64 * 68;   // [64][68]  Pt[j][i]
    float* sq = smem + 4 * 64 * 68;   // [64]
    float* sk = sq + 64;              // [64]

    const int tid = threadIdx.x;
    const int tx  = tid & 15;
    const int ty  = tid >> 4;
    const int m   = blockIdx.y;       // head 0..31
    const int q0  = blockIdx.x * 64;

    // Load Q tile transposed: Qt[d][i]
    const float* Qg = g_Q + ((size_t)m * S_LEN + q0) * DHEAD;
    {
        int r  = tid >> 4;            // 0..15
        int dq = (tid & 15) * 4;
        #pragma unroll
        for (int p = 0; p < 4; ++p) {
            int row = r + p * 16;
            float4 v = *(const float4*)(Qg + row * 64 + dq);
            Qt[(dq + 0) * 68 + row] = v.x;
            Qt[(dq + 1) * 68 + row] = v.y;
            Qt[(dq + 2) * 68 + row] = v.z;
            Qt[(dq + 3) * 68 + row] = v.w;
        }
    }
    __syncthreads();
    if (tid < 64) {
        float s = 0.f;
        #pragma unroll
        for (int d = 0; d < 64; ++d) { float q = Qt[d * 68 + tid]; s = fmaf(q, q, s); }
        sq[tid] = s;
    }

    float ctx[4][4];
    #pragma unroll
    for (int i = 0; i < 4; ++i)
        #pragma unroll
        for (int c = 0; c < 4; ++c) ctx[i][c] = 0.f;

    for (int t0 = 0; t0 < S_LEN; t0 += 64) {
        __syncthreads();   // previous-iteration readers done (also orders sq)

        const float* Kg = g_K + ((size_t)m * S_LEN + t0) * DHEAD;
        const float* Vg = g_V + ((size_t)m * S_LEN + t0) * DHEAD;
        {
            int r  = tid >> 4;
            int dq = (tid & 15) * 4;
            #pragma unroll
            for (int p = 0; p < 4; ++p) {
                int row = r + p * 16;
                float4 v = *(const float4*)(Kg + row * 64 + dq);
                Kt[(dq + 0) * 68 + row] = v.x;
                Kt[(dq + 1) * 68 + row] = v.y;
                Kt[(dq + 2) * 68 + row] = v.z;
                Kt[(dq + 3) * 68 + row] = v.w;
                float4 w = *(const float4*)(Vg + row * 64 + dq);
                *(float4*)(Vs + row * 68 + dq) = w;
            }
        }
        __syncthreads();
        if (tid < 64) {
            float s = 0.f;
            #pragma unroll
            for (int d = 0; d < 64; ++d) { float k = Kt[d * 68 + tid]; s = fmaf(k, k, s); }
            sk[tid] = s;
        }
        __syncthreads();

        // GEMM1: acc[i][j] = sum_d Q[q0+ty*4+i][d] * K[t0+tx*4+j][d]
        float acc[4][4];
        #pragma unroll
        for (int i = 0; i < 4; ++i)
            #pragma unroll
            for (int j = 0; j < 4; ++j) acc[i][j] = 0.f;

        #pragma unroll 8
        for (int d = 0; d < 64; ++d) {
            float4 qv = *(const float4*)(Qt + d * 68 + ty * 4);
            float4 kv = *(const float4*)(Kt + d * 68 + tx * 4);
            float qa[4] = {qv.x, qv.y, qv.z, qv.w};
            float ka[4] = {kv.x, kv.y, kv.z, kv.w};
            #pragma unroll
            for (int i = 0; i < 4; ++i)
                #pragma unroll
                for (int j = 0; j < 4; ++j)
                    acc[i][j] = fmaf(qa[i], ka[j], acc[i][j]);
        }

        // Scores + exp + write
        float sqr[4], skr[4];
        #pragma unroll
        for (int i = 0; i < 4; ++i) sqr[i] = sq[ty * 4 + i];
        #pragma unroll
        for (int j = 0; j < 4; ++j) skr[j] = sk[tx * 4 + j];

        #pragma unroll
        for (int i = 0; i < 4; ++i) {
            float4 sc;
            sc.x = (sqr[i] + skr[0] - 2.f * acc[i][0]) * -0.0625f;
            sc.y = (sqr[i] + skr[1] - 2.f * acc[i][1]) * -0.0625f;
            sc.z = (sqr[i] + skr[2] - 2.f * acc[i][2]) * -0.0625f;
            sc.w = (sqr[i] + skr[3] - 2.f * acc[i][3]) * -0.0625f;
            *(float4*)(score_out + ((size_t)m * S_LEN + q0 + ty * 4 + i) * S_LEN
                                 + t0 + tx * 4) = sc;
            Pt[(tx * 4 + 0) * 68 + ty * 4 + i] = __expf(sc.x);
            Pt[(tx * 4 + 1) * 68 + ty * 4 + i] = __expf(sc.y);
            Pt[(tx * 4 + 2) * 68 + ty * 4 + i] = __expf(sc.z);
            Pt[(tx * 4 + 3) * 68 + ty * 4 + i] = __expf(sc.w);
        }
        __syncthreads();

        // GEMM2: ctx[i][c] += sum_j P[q-row i][j] * V[j][d-col c]
        #pragma unroll 8
        for (int j = 0; j < 64; ++j) {
            float4 pv = *(const float4*)(Pt + j * 68 + ty * 4);
            float4 vv = *(const float4*)(Vs + j * 68 + tx * 4);
            float pa[4] = {pv.x, pv.y, pv.z, pv.w};
            float va[4] = {vv.x, vv.y, vv.z, vv.w};
            #pragma unroll
            for (int i = 0; i < 4; ++i)
                #pragma unroll
                for (int c = 0; c < 4; ++c)
                    ctx[i][c] = fmaf(pa[i], va[c], ctx[i][c]);
        }
    }

    // Write ctx: [s][b][head*64+d]
    const int b = m >> 4;
    const int h = m & 15;
    #pragma unroll
    for (int i = 0; i < 4; ++i) {
        size_t off = ((size_t)(q0 + ty * 4 + i) * BATCH + b) * HID + h * 64 + tx * 4;
        float4 v = make_float4(ctx[i][0], ctx[i][1], ctx[i][2], ctx[i][3]);
        *(float4*)(ctx_out + off) = v;
    }
}

// ---------------------------------------------------------------------------
extern "C" void kernel_launch(void* const* d_in, const int* in_sizes, int n_in,
                              void* d_out, int out_size)
{
    const float* hidden = (const float*)d_in[0];   // [S][B][H]
    const float* W      = (const float*)d_in[1];   // [3H][H]
    const float* bias   = (const float*)d_in[2];   // [3H]

    float* ctx_out   = (float*)d_out;                              // [S][B][H]
    float* score_out = ctx_out + (size_t)S_LEN * BATCH * HID;      // [M][S][S]

    dim3 g1(N_DIM / 128, M_DIM / 128);
    qkv_gemm_kernel<<<g1, 256>>>(hidden, W, bias);

    const int attn_smem = (4 * 64 * 68 + 128) * (int)sizeof(float);  // 70144 B
    cudaFuncSetAttribute(attn_kernel, cudaFuncAttributeMaxDynamicSharedMemorySize,
                         attn_smem);
    dim3 g2(S_LEN / 64, MHEADS);
    attn_kernel<<<g2, 256, attn_smem>>>(ctx_out, score_out);
}

// round 4
// speedup vs baseline: 2.3479x; 2.3479x over previous
#include <cuda_runtime.h>
#include <cuda_bf16.h>
#include <cstdint>

#define S_LEN  2048
#define BATCH  2
#define HID    1024
#define DHEAD  64
#define MHEADS 32
#define K_DIM  1024
#define N_DIM  3072
#define M_DIM  4096

// ---------------- scratch (__device__ globals) ----------------
__device__ __nv_bfloat16 g_hid_hi[(size_t)M_DIM * K_DIM];
__device__ __nv_bfloat16 g_hid_lo[(size_t)M_DIM * K_DIM];
__device__ __nv_bfloat16 g_w_hi[(size_t)N_DIM * K_DIM];
__device__ __nv_bfloat16 g_w_lo[(size_t)N_DIM * K_DIM];
__device__ __nv_bfloat16 g_Qhi[(size_t)MHEADS * S_LEN * DHEAD];
__device__ __nv_bfloat16 g_Qlo[(size_t)MHEADS * S_LEN * DHEAD];
__device__ __nv_bfloat16 g_Khi[(size_t)MHEADS * S_LEN * DHEAD];
__device__ __nv_bfloat16 g_Klo[(size_t)MHEADS * S_LEN * DHEAD];
__device__ __nv_bfloat16 g_Vhi[(size_t)MHEADS * S_LEN * DHEAD];
__device__ __nv_bfloat16 g_Vlo[(size_t)MHEADS * S_LEN * DHEAD];
__device__ float g_sq[(size_t)MHEADS * S_LEN];
__device__ float g_sk[(size_t)MHEADS * S_LEN];

// ---------------- helpers ----------------
#define SWZ(o) ((o) ^ (((o) >> 3) & 0x70))

__device__ __forceinline__ uint32_t smem_u32(const void* p) {
    uint32_t a;
    asm("{ .reg .u64 t; cvta.to.shared.u64 t, %1; cvt.u32.u64 %0, t; }" : "=r"(a) : "l"(p));
    return a;
}
__device__ __forceinline__ void ldsm4(uint32_t r[4], uint32_t a) {
    asm volatile("ldmatrix.sync.aligned.m8n8.x4.shared.b16 {%0,%1,%2,%3}, [%4];"
        : "=r"(r[0]), "=r"(r[1]), "=r"(r[2]), "=r"(r[3]) : "r"(a));
}
__device__ __forceinline__ void ldsm4t(uint32_t r[4], uint32_t a) {
    asm volatile("ldmatrix.sync.aligned.m8n8.x4.trans.shared.b16 {%0,%1,%2,%3}, [%4];"
        : "=r"(r[0]), "=r"(r[1]), "=r"(r[2]), "=r"(r[3]) : "r"(a));
}
__device__ __forceinline__ void mma_bf16(float c[4], const uint32_t a[4],
                                         uint32_t b0, uint32_t b1) {
    asm volatile("mma.sync.aligned.m16n8k16.row.col.f32.bf16.bf16.f32 "
        "{%0,%1,%2,%3}, {%4,%5,%6,%7}, {%8,%9}, {%0,%1,%2,%3};"
        : "+f"(c[0]), "+f"(c[1]), "+f"(c[2]), "+f"(c[3])
        : "r"(a[0]), "r"(a[1]), "r"(a[2]), "r"(a[3]), "r"(b0), "r"(b1));
}
__device__ __forceinline__ void split2(float x, float y, uint32_t& hi, uint32_t& lo) {
    __nv_bfloat16 hx = __float2bfloat16(x), hy = __float2bfloat16(y);
    __nv_bfloat16 lx = __float2bfloat16(x - __bfloat162float(hx));
    __nv_bfloat16 ly = __float2bfloat16(y - __bfloat162float(hy));
    hi = (uint32_t)__bfloat16_as_ushort(hx) | ((uint32_t)__bfloat16_as_ushort(hy) << 16);
    lo = (uint32_t)__bfloat16_as_ushort(lx) | ((uint32_t)__bfloat16_as_ushort(ly) << 16);
}

// ---------------- K1: fp32 -> bf16 hi/lo ----------------
__global__ __launch_bounds__(256) void convert_kernel(const float* __restrict__ src,
                                                      int n4, int which)
{
    __nv_bfloat16* hi = which ? g_w_hi : g_hid_hi;
    __nv_bfloat16* lo = which ? g_w_lo : g_hid_lo;
    for (int i = blockIdx.x * blockDim.x + threadIdx.x; i < n4;
         i += gridDim.x * blockDim.x) {
        float4 v = ((const float4*)src)[i];
        uint32_t h0, l0, h1, l1;
        split2(v.x, v.y, h0, l0);
        split2(v.z, v.w, h1, l1);
        ((uint2*)hi)[i] = make_uint2(h0, h1);
        ((uint2*)lo)[i] = make_uint2(l0, l1);
    }
}

// ---------------- K2: QKV GEMM (HMMA bf16x3) ----------------
// smem: Ahi 0, Alo 16K, Bhi 32K, Blo 48K  (tiles [128][64] bf16, swizzled)
#define QSMEM 65536

__global__ __launch_bounds__(256, 2) void qkv_hmma(const float* __restrict__ bias)
{
    extern __shared__ char sm[];
    const uint32_t sb = smem_u32(sm);
    const int tid = threadIdx.x, wid = tid >> 5, lane = tid & 31;
    const int n0 = blockIdx.x * 128, m0 = blockIdx.y * 128;
    const int wm = wid >> 1, wn = wid & 1;
    const int lr16 = lane & 15, lk8 = (lane >> 4) << 3;
    const int qr = lane >> 2, qc = (lane & 3) * 2;

    float acc[2][8][4];
    #pragma unroll
    for (int mt = 0; mt < 2; ++mt)
        #pragma unroll
        for (int nt = 0; nt < 8; ++nt)
            #pragma unroll
            for (int c = 0; c < 4; ++c) acc[mt][nt][c] = 0.f;

    for (int kc = 0; kc < 16; ++kc) {
        const int k0 = kc * 64;
        if (kc) __syncthreads();
        #pragma unroll
        for (int g = 0; g < 4; ++g) {
            const __nv_bfloat16* base = (g == 0) ? g_hid_hi : (g == 1) ? g_hid_lo
                                      : (g == 2) ? g_w_hi : g_w_lo;
            const int rb = (g < 2) ? m0 : n0;
            char* dst = sm + g * 16384;
            #pragma unroll
            for (int i = 0; i < 4; ++i) {
                int u = tid + i * 256;
                int row = u >> 3, c16 = u & 7;
                uint4 v = *((const uint4*)(base + (size_t)(rb + row) * K_DIM + k0) + c16);
                uint32_t byte = row * 128 + c16 * 16;
                *(uint4*)(dst + SWZ(byte)) = v;
            }
        }
        __syncthreads();

        #pragma unroll
        for (int ks = 0; ks < 4; ++ks) {
            const uint32_t kb = (ks * 16 + lk8) * 2;
            uint32_t ahi[2][4], alo[2][4];
            #pragma unroll
            for (int mt = 0; mt < 2; ++mt) {
                uint32_t byte = (wm * 32 + mt * 16 + lr16) * 128 + kb;
                ldsm4(ahi[mt], sb + SWZ(byte));
                ldsm4(alo[mt], sb + 16384 + SWZ(byte));
            }
            #pragma unroll
            for (int np = 0; np < 4; ++np) {
                uint32_t byte = (wn * 64 + np * 16 + lr16) * 128 + kb;
                uint32_t bh[4], bl[4];
                ldsm4(bh, sb + 32768 + SWZ(byte));
                ldsm4(bl, sb + 49152 + SWZ(byte));
                #pragma unroll
                for (int h = 0; h < 2; ++h)
                    #pragma unroll
                    for (int mt = 0; mt < 2; ++mt) {
                        float* c = acc[mt][np * 2 + h];
                        mma_bf16(c, ahi[mt], bh[h], bh[h + 2]);
                        mma_bf16(c, ahi[mt], bl[h], bl[h + 2]);
                        mma_bf16(c, alo[mt], bh[h], bh[h + 2]);
                    }
            }
        }
    }

    // epilogue: bias, bf16 split, scatter, exact norms
    const int nbase = n0 + wn * 64;
    const int head = nbase / 192;
    const int wsel = nbase - head * 192;
    const int sel = wsel >> 6;
    __nv_bfloat16* oh = (sel == 0) ? g_Qhi : (sel == 1) ? g_Khi : g_Vhi;
    __nv_bfloat16* ol = (sel == 0) ? g_Qlo : (sel == 1) ? g_Klo : g_Vlo;

    #pragma unroll
    for (int mt = 0; mt < 2; ++mt) {
        const int rA = m0 + wm * 32 + mt * 16 + qr;
        const int rB = rA + 8;
        float sumA = 0.f, sumB = 0.f;
        uint32_t hiA[8], loA[8], hiB[8], loB[8];
        #pragma unroll
        for (int nt = 0; nt < 8; ++nt) {
            const float* c = acc[mt][nt];
            const int n = nbase + nt * 8 + qc;
            float b0 = __ldg(bias + n), b1 = __ldg(bias + n + 1);
            float v00 = c[0] + b0, v01 = c[1] + b1;
            float v10 = c[2] + b0, v11 = c[3] + b1;
            sumA = fmaf(v00, v00, fmaf(v01, v01, sumA));
            sumB = fmaf(v10, v10, fmaf(v11, v11, sumB));
            split2(v00, v01, hiA[nt], loA[nt]);
            split2(v10, v11, hiB[nt], loB[nt]);
        }
        const int sA = rA >> 1, mhA = (rA & 1) * 16 + head;
        const int sB = rB >> 1, mhB = (rB & 1) * 16 + head;
        const size_t offA = ((size_t)mhA * S_LEN + sA) * DHEAD;
        const size_t offB = ((size_t)mhB * S_LEN + sB) * DHEAD;
        #pragma unroll
        for (int nt = 0; nt < 8; ++nt) {
            int d = nt * 8 + qc;
            *(uint32_t*)(oh + offA + d) = hiA[nt];
            *(uint32_t*)(ol + offA + d) = loA[nt];
            *(uint32_t*)(oh + offB + d) = hiB[nt];
            *(uint32_t*)(ol + offB + d) = loB[nt];
        }
        sumA += __shfl_xor_sync(0xffffffffu, sumA, 1);
        sumA += __shfl_xor_sync(0xffffffffu, sumA, 2);
        sumB += __shfl_xor_sync(0xffffffffu, sumB, 1);
        sumB += __shfl_xor_sync(0xffffffffu, sumB, 2);
        if ((lane & 3) == 0 && sel < 2) {
            float* dst = sel ? g_sk : g_sq;
            dst[(size_t)mhA * S_LEN + sA] = sumA;
            dst[(size_t)mhB * S_LEN + sB] = sumB;
        }
    }
}

// ---------------- K3: attention (HMMA bf16x3) ----------------
#define A_QHI 0
#define A_QLO 16384
#define A_KHI 32768
#define A_KLO 40960
#define A_VHI 49152
#define A_VLO 57344
#define A_PHI 65536
#define A_PLO 81920
#define A_SK  98304
#define ASMEM 98560

__global__ __launch_bounds__(256, 2) void attn_hmma(float* __restrict__ ctx_out,
                                                    float* __restrict__ score_out)
{
    extern __shared__ char sm[];
    const uint32_t sb = smem_u32(sm);
    const int tid = threadIdx.x, wid = tid >> 5, lane = tid & 31;
    const int m = blockIdx.y, q0 = blockIdx.x * 128;
    const int wm = wid >> 1, wn = wid & 1;
    const int lr16 = lane & 15, lk8 = (lane >> 4) << 3;
    const int qr = lane >> 2, qc = (lane & 3) * 2;

    // load Q hi/lo tiles (swizzled)
    #pragma unroll
    for (int g = 0; g < 2; ++g) {
        const __nv_bfloat16* base = g ? g_Qlo : g_Qhi;
        char* dst = sm + (g ? A_QLO : A_QHI);
        #pragma unroll
        for (int i = 0; i < 4; ++i) {
            int u = tid + i * 256;
            int row = u >> 3, c16 = u & 7;
            uint4 v = *((const uint4*)(base + ((size_t)m * S_LEN + q0 + row) * DHEAD) + c16);
            uint32_t byte = row * 128 + c16 * 16;
            *(uint4*)(dst + SWZ(byte)) = v;
        }
    }

    float sqr[2][2];
    #pragma unroll
    for (int mt = 0; mt < 2; ++mt) {
        sqr[mt][0] = g_sq[(size_t)m * S_LEN + q0 + wm * 32 + mt * 16 + qr];
        sqr[mt][1] = g_sq[(size_t)m * S_LEN + q0 + wm * 32 + mt * 16 + qr + 8];
    }

    float ctx[2][4][4];
    #pragma unroll
    for (int mt = 0; mt < 2; ++mt)
        #pragma unroll
        for (int nt = 0; nt < 4; ++nt)
            #pragma unroll
            for (int c = 0; c < 4; ++c) ctx[mt][nt][c] = 0.f;

    for (int t = 0; t < 32; ++t) {
        const int t0 = t * 64;
        __syncthreads();   // prior GEMM2 readers done
        #pragma unroll
        for (int g = 0; g < 4; ++g) {
            const __nv_bfloat16* base = (g == 0) ? g_Khi : (g == 1) ? g_Klo
                                      : (g == 2) ? g_Vhi : g_Vlo;
            char* dst = sm + A_KHI + g * 8192;
            #pragma unroll
            for (int i = 0; i < 2; ++i) {
                int u = tid + i * 256;
                int row = u >> 3, c16 = u & 7;
                uint4 v = *((const uint4*)(base + ((size_t)m * S_LEN + t0 + row) * DHEAD) + c16);
                uint32_t byte = row * 128 + c16 * 16;
                *(uint4*)(dst + SWZ(byte)) = v;
            }
        }
        if (tid < 64) ((float*)(sm + A_SK))[tid] = g_sk[(size_t)m * S_LEN + t0 + tid];
        __syncthreads();

        // ---- GEMM1: S = Q·K^T (bf16x3) ----
        float sacc[2][4][4];
        #pragma unroll
        for (int mt = 0; mt < 2; ++mt)
            #pragma unroll
            for (int nt = 0; nt < 4; ++nt)
                #pragma unroll
                for (int c = 0; c < 4; ++c) sacc[mt][nt][c] = 0.f;

        #pragma unroll
        for (int ks = 0; ks < 4; ++ks) {
            const uint32_t kb = (ks * 16 + lk8) * 2;
            uint32_t ahi[2][4], alo[2][4];
            #pragma unroll
            for (int mt = 0; mt < 2; ++mt) {
                uint32_t byte = (wm * 32 + mt * 16 + lr16) * 128 + kb;
                ldsm4(ahi[mt], sb + A_QHI + SWZ(byte));
                ldsm4(alo[mt], sb + A_QLO + SWZ(byte));
            }
            #pragma unroll
            for (int np = 0; np < 2; ++np) {
                uint32_t byte = (wn * 32 + np * 16 + lr16) * 128 + kb;
                uint32_t bh[4], bl[4];
                ldsm4(bh, sb + A_KHI + SWZ(byte));
                ldsm4(bl, sb + A_KLO + SWZ(byte));
                #pragma unroll
                for (int h = 0; h < 2; ++h)
                    #pragma unroll
                    for (int mt = 0; mt < 2; ++mt) {
                        float* c = sacc[mt][np * 2 + h];
                        mma_bf16(c, ahi[mt], bh[h], bh[h + 2]);
                        mma_bf16(c, ahi[mt], bl[h], bl[h + 2]);
                        mma_bf16(c, alo[mt], bh[h], bh[h + 2]);
                    }
            }
        }

        // ---- epilogue: scores + exp + P to smem ----
        const float* skp = (const float*)(sm + A_SK);
        #pragma unroll
        for (int mt = 0; mt < 2; ++mt) {
            const int rl = wm * 32 + mt * 16 + qr;
            float* srowA = score_out + ((size_t)m * S_LEN + q0 + rl) * S_LEN + t0;
            float* srowB = srowA + 8 * S_LEN;
            #pragma unroll
            for (int nt = 0; nt < 4; ++nt) {
                const float* c = sacc[mt][nt];
                const int cg = wn * 32 + nt * 8 + qc;
                float k0v = skp[cg], k1v = skp[cg + 1];
                float s00 = (sqr[mt][0] + k0v - 2.f * c[0]) * -0.0625f;
                float s01 = (sqr[mt][0] + k1v - 2.f * c[1]) * -0.0625f;
                float s10 = (sqr[mt][1] + k0v - 2.f * c[2]) * -0.0625f;
                float s11 = (sqr[mt][1] + k1v - 2.f * c[3]) * -0.0625f;
                *(float2*)(srowA + cg) = make_float2(s00, s01);
                *(float2*)(srowB + cg) = make_float2(s10, s11);
                float p00 = __expf(s00), p01 = __expf(s01);
                float p10 = __expf(s10), p11 = __expf(s11);
                uint32_t hA, lA, hB, lB;
                split2(p00, p01, hA, lA);
                split2(p10, p11, hB, lB);
                uint32_t byteA = rl * 128 + cg * 2;
                uint32_t byteB = (rl + 8) * 128 + cg * 2;
                *(uint32_t*)(sm + A_PHI + SWZ(byteA)) = hA;
                *(uint32_t*)(sm + A_PLO + SWZ(byteA)) = lA;
                *(uint32_t*)(sm + A_PHI + SWZ(byteB)) = hB;
                *(uint32_t*)(sm + A_PLO + SWZ(byteB)) = lB;
            }
        }
        __syncthreads();

        // ---- GEMM2: ctx += P·V (bf16x3, V via ldmatrix.trans) ----
        #pragma unroll
        for (int ks = 0; ks < 4; ++ks) {
            const uint32_t kb = (ks * 16 + lk8) * 2;
            uint32_t phi[2][4], plo[2][4];
            #pragma unroll
            for (int mt = 0; mt < 2; ++mt) {
                uint32_t byte = (wm * 32 + mt * 16 + lr16) * 128 + kb;
                ldsm4(phi[mt], sb + A_PHI + SWZ(byte));
                ldsm4(plo[mt], sb + A_PLO + SWZ(byte));
            }
            const int kt = ks * 16 + (lane & 7) + lk8;
            #pragma unroll
            for (int np = 0; np < 2; ++np) {
                const int nb = wn * 32 + np * 16 + (lane & 8);
                uint32_t byte = kt * 128 + nb * 2;
                uint32_t vh[4], vl[4];
                ldsm4t(vh, sb + A_VHI + SWZ(byte));
                ldsm4t(vl, sb + A_VLO + SWZ(byte));
                #pragma unroll
                for (int h = 0; h < 2; ++h)
                    #pragma unroll
                    for (int mt = 0; mt < 2; ++mt) {
                        float* c = ctx[mt][np * 2 + h];
                        mma_bf16(c, phi[mt], vh[h], vh[h + 2]);
                        mma_bf16(c, phi[mt], vl[h], vl[h + 2]);
                        mma_bf16(c, plo[mt], vh[h], vh[h + 2]);
                    }
            }
        }
    }

    // ---- write ctx: [s][b][head*64+d] ----
    const int bb = m >> 4, hh = m & 15;
    #pragma unroll
    for (int mt = 0; mt < 2; ++mt) {
        const int rl = wm * 32 + mt * 16 + qr;
        #pragma unroll
        for (int nt = 0; nt < 4; ++nt) {
            const float* c = ctx[mt][nt];
            const int d = wn * 32 + nt * 8 + qc;
            float* dA = ctx_out + ((size_t)(q0 + rl) * BATCH + bb) * HID + hh * 64 + d;
            float* dB = ctx_out + ((size_t)(q0 + rl + 8) * BATCH + bb) * HID + hh * 64 + d;
            *(float2*)dA = make_float2(c[0], c[1]);
            *(float2*)dB = make_float2(c[2], c[3]);
        }
    }
}

// ---------------------------------------------------------------------------
extern "C" void kernel_launch(void* const* d_in, const int* in_sizes, int n_in,
                              void* d_out, int out_size)
{
    const float* hidden = (const float*)d_in[0];
    const float* W      = (const float*)d_in[1];
    const float* bias   = (const float*)d_in[2];
    float* ctx_out   = (float*)d_out;
    float* score_out = ctx_out + (size_t)S_LEN * BATCH * HID;

    convert_kernel<<<1024, 256>>>(hidden, M_DIM * K_DIM / 4, 0);
    convert_kernel<<<1024, 256>>>(W,      N_DIM * K_DIM / 4, 1);

    cudaFuncSetAttribute(qkv_hmma, cudaFuncAttributeMaxDynamicSharedMemorySize, QSMEM);
    dim3 g1(N_DIM / 128, M_DIM / 128);
    qkv_hmma<<<g1, 256, QSMEM>>>(bias);

    cudaFuncSetAttribute(attn_hmma, cudaFuncAttributeMaxDynamicSharedMemorySize, ASMEM);
    dim3 g2(S_LEN / 128, MHEADS);
    attn_hmma<<<g2, 256, ASMEM>>>(ctx_out, score_out);
}

// round 5
// speedup vs baseline: 2.9476x; 1.2554x over previous
#include <cuda_runtime.h>
#include <cuda_bf16.h>
#include <cuda_fp16.h>
#include <cstdint>

#define S_LEN  2048
#define BATCH  2
#define HID    1024
#define DHEAD  64
#define MHEADS 32
#define K_DIM  1024
#define N_DIM  3072
#define M_DIM  4096

// ---------------- scratch (__device__ globals) ----------------
__device__ __nv_bfloat16 g_hid_hi[(size_t)M_DIM * K_DIM];
__device__ __nv_bfloat16 g_hid_lo[(size_t)M_DIM * K_DIM];
__device__ __nv_bfloat16 g_w_hi[(size_t)N_DIM * K_DIM];
__device__ __nv_bfloat16 g_w_lo[(size_t)N_DIM * K_DIM];
__device__ __nv_bfloat16 g_Qhi[(size_t)MHEADS * S_LEN * DHEAD];
__device__ __nv_bfloat16 g_Qlo[(size_t)MHEADS * S_LEN * DHEAD];
__device__ __nv_bfloat16 g_Khi[(size_t)MHEADS * S_LEN * DHEAD];
__device__ __nv_bfloat16 g_Klo[(size_t)MHEADS * S_LEN * DHEAD];
__device__ __half        g_Vh [(size_t)MHEADS * S_LEN * DHEAD];
__device__ __half        g_Vl [(size_t)MHEADS * S_LEN * DHEAD];
__device__ float g_sq[(size_t)MHEADS * S_LEN];
__device__ float g_sk[(size_t)MHEADS * S_LEN];

// ---------------- helpers ----------------
#define SWZ(o) ((o) ^ (((o) >> 3) & 0x70))

__device__ __forceinline__ uint32_t smem_u32(const void* p) {
    uint32_t a;
    asm("{ .reg .u64 t; cvta.to.shared.u64 t, %1; cvt.u32.u64 %0, t; }" : "=r"(a) : "l"(p));
    return a;
}
__device__ __forceinline__ void ldsm4(uint32_t r[4], uint32_t a) {
    asm volatile("ldmatrix.sync.aligned.m8n8.x4.shared.b16 {%0,%1,%2,%3}, [%4];"
        : "=r"(r[0]), "=r"(r[1]), "=r"(r[2]), "=r"(r[3]) : "r"(a));
}
__device__ __forceinline__ void ldsm4t(uint32_t r[4], uint32_t a) {
    asm volatile("ldmatrix.sync.aligned.m8n8.x4.trans.shared.b16 {%0,%1,%2,%3}, [%4];"
        : "=r"(r[0]), "=r"(r[1]), "=r"(r[2]), "=r"(r[3]) : "r"(a));
}
__device__ __forceinline__ void mma_bf16(float c[4], const uint32_t a[4],
                                         uint32_t b0, uint32_t b1) {
    asm volatile("mma.sync.aligned.m16n8k16.row.col.f32.bf16.bf16.f32 "
        "{%0,%1,%2,%3}, {%4,%5,%6,%7}, {%8,%9}, {%0,%1,%2,%3};"
        : "+f"(c[0]), "+f"(c[1]), "+f"(c[2]), "+f"(c[3])
        : "r"(a[0]), "r"(a[1]), "r"(a[2]), "r"(a[3]), "r"(b0), "r"(b1));
}
__device__ __forceinline__ void mma_f16(float c[4], const uint32_t a[4],
                                        uint32_t b0, uint32_t b1) {
    asm volatile("mma.sync.aligned.m16n8k16.row.col.f32.f16.f16.f32 "
        "{%0,%1,%2,%3}, {%4,%5,%6,%7}, {%8,%9}, {%0,%1,%2,%3};"
        : "+f"(c[0]), "+f"(c[1]), "+f"(c[2]), "+f"(c[3])
        : "r"(a[0]), "r"(a[1]), "r"(a[2]), "r"(a[3]), "r"(b0), "r"(b1));
}
__device__ __forceinline__ void split2(float x, float y, uint32_t& hi, uint32_t& lo) {
    __nv_bfloat16 hx = __float2bfloat16(x), hy = __float2bfloat16(y);
    __nv_bfloat16 lx = __float2bfloat16(x - __bfloat162float(hx));
    __nv_bfloat16 ly = __float2bfloat16(y - __bfloat162float(hy));
    hi = (uint32_t)__bfloat16_as_ushort(hx) | ((uint32_t)__bfloat16_as_ushort(hy) << 16);
    lo = (uint32_t)__bfloat16_as_ushort(lx) | ((uint32_t)__bfloat16_as_ushort(ly) << 16);
}
__device__ __forceinline__ void split2h(float x, float y, uint32_t& hi, uint32_t& lo) {
    __half hx = __float2half_rn(x), hy = __float2half_rn(y);
    __half lx = __float2half_rn(x - __half2float(hx));
    __half ly = __float2half_rn(y - __half2float(hy));
    __half2 h = __halves2half2(hx, hy), l = __halves2half2(lx, ly);
    hi = *reinterpret_cast<uint32_t*>(&h);
    lo = *reinterpret_cast<uint32_t*>(&l);
}
#define CP16(dst, src) asm volatile("cp.async.cg.shared.global [%0], [%1], 16;" :: "r"(dst), "l"(src))
#define CP_COMMIT()    asm volatile("cp.async.commit_group;" ::: "memory")
#define CP_WAIT0()     asm volatile("cp.async.wait_group 0;" ::: "memory")

// ---------------- K1: fp32 -> bf16 hi/lo ----------------
__global__ __launch_bounds__(256) void convert_kernel(const float* __restrict__ src,
                                                      int n4, int which)
{
    __nv_bfloat16* hi = which ? g_w_hi : g_hid_hi;
    __nv_bfloat16* lo = which ? g_w_lo : g_hid_lo;
    for (int i = blockIdx.x * blockDim.x + threadIdx.x; i < n4;
         i += gridDim.x * blockDim.x) {
        float4 v = ((const float4*)src)[i];
        uint32_t h0, l0, h1, l1;
        split2(v.x, v.y, h0, l0);
        split2(v.z, v.w, h1, l1);
        ((uint2*)hi)[i] = make_uint2(h0, h1);
        ((uint2*)lo)[i] = make_uint2(l0, l1);
    }
}

// ---------------- K2: QKV GEMM (HMMA bf16x3) ----------------
#define QSMEM 65536

__global__ __launch_bounds__(256, 2) void qkv_hmma(const float* __restrict__ bias)
{
    extern __shared__ char sm[];
    const uint32_t sb = smem_u32(sm);
    const int tid = threadIdx.x, wid = tid >> 5, lane = tid & 31;
    const int n0 = blockIdx.x * 128, m0 = blockIdx.y * 128;
    const int wm = wid >> 1, wn = wid & 1;
    const int lr16 = lane & 15, lk8 = (lane >> 4) << 3;
    const int qr = lane >> 2, qc = (lane & 3) * 2;

    float acc[2][8][4];
    #pragma unroll
    for (int mt = 0; mt < 2; ++mt)
        #pragma unroll
        for (int nt = 0; nt < 8; ++nt)
            #pragma unroll
            for (int c = 0; c < 4; ++c) acc[mt][nt][c] = 0.f;

    for (int kc = 0; kc < 16; ++kc) {
        const int k0 = kc * 64;
        if (kc) __syncthreads();
        #pragma unroll
        for (int g = 0; g < 4; ++g) {
            const __nv_bfloat16* base = (g == 0) ? g_hid_hi : (g == 1) ? g_hid_lo
                                      : (g == 2) ? g_w_hi : g_w_lo;
            const int rb = (g < 2) ? m0 : n0;
            char* dst = sm + g * 16384;
            #pragma unroll
            for (int i = 0; i < 4; ++i) {
                int u = tid + i * 256;
                int row = u >> 3, c16 = u & 7;
                uint4 v = *((const uint4*)(base + (size_t)(rb + row) * K_DIM + k0) + c16);
                uint32_t byte = row * 128 + c16 * 16;
                *(uint4*)(dst + SWZ(byte)) = v;
            }
        }
        __syncthreads();

        #pragma unroll
        for (int ks = 0; ks < 4; ++ks) {
            const uint32_t kb = (ks * 16 + lk8) * 2;
            uint32_t ahi[2][4], alo[2][4];
            #pragma unroll
            for (int mt = 0; mt < 2; ++mt) {
                uint32_t byte = (wm * 32 + mt * 16 + lr16) * 128 + kb;
                ldsm4(ahi[mt], sb + SWZ(byte));
                ldsm4(alo[mt], sb + 16384 + SWZ(byte));
            }
            #pragma unroll
            for (int np = 0; np < 4; ++np) {
                uint32_t byte = (wn * 64 + np * 16 + lr16) * 128 + kb;
                uint32_t bh[4], bl[4];
                ldsm4(bh, sb + 32768 + SWZ(byte));
                ldsm4(bl, sb + 49152 + SWZ(byte));
                #pragma unroll
                for (int h = 0; h < 2; ++h)
                    #pragma unroll
                    for (int mt = 0; mt < 2; ++mt) {
                        float* c = acc[mt][np * 2 + h];
                        mma_bf16(c, ahi[mt], bh[h], bh[h + 2]);
                        mma_bf16(c, ahi[mt], bl[h], bl[h + 2]);
                        mma_bf16(c, alo[mt], bh[h], bh[h + 2]);
                    }
            }
        }
    }

    // epilogue
    const int nbase = n0 + wn * 64;
    const int head = nbase / 192;
    const int wsel = nbase - head * 192;
    const int sel = wsel >> 6;

    #pragma unroll
    for (int mt = 0; mt < 2; ++mt) {
        const int rA = m0 + wm * 32 + mt * 16 + qr;
        const int rB = rA + 8;
        const int sA = rA >> 1, mhA = (rA & 1) * 16 + head;
        const int sB = rB >> 1, mhB = (rB & 1) * 16 + head;
        const size_t offA = ((size_t)mhA * S_LEN + sA) * DHEAD;
        const size_t offB = ((size_t)mhB * S_LEN + sB) * DHEAD;
        if (sel == 2) {
            #pragma unroll
            for (int nt = 0; nt < 8; ++nt) {
                const float* c = acc[mt][nt];
                const int n = nbase + nt * 8 + qc;
                float b0 = __ldg(bias + n), b1 = __ldg(bias + n + 1);
                uint32_t hA, lA, hB, lB;
                split2h(c[0] + b0, c[1] + b1, hA, lA);
                split2h(c[2] + b0, c[3] + b1, hB, lB);
                int d = nt * 8 + qc;
                *(uint32_t*)(g_Vh + offA + d) = hA;
                *(uint32_t*)(g_Vl + offA + d) = lA;
                *(uint32_t*)(g_Vh + offB + d) = hB;
                *(uint32_t*)(g_Vl + offB + d) = lB;
            }
        } else {
            __nv_bfloat16* oh = sel ? g_Khi : g_Qhi;
            __nv_bfloat16* ol = sel ? g_Klo : g_Qlo;
            float sumA = 0.f, sumB = 0.f;
            #pragma unroll
            for (int nt = 0; nt < 8; ++nt) {
                const float* c = acc[mt][nt];
                const int n = nbase + nt * 8 + qc;
                float b0 = __ldg(bias + n), b1 = __ldg(bias + n + 1);
                float v00 = c[0] + b0, v01 = c[1] + b1;
                float v10 = c[2] + b0, v11 = c[3] + b1;
                sumA = fmaf(v00, v00, fmaf(v01, v01, sumA));
                sumB = fmaf(v10, v10, fmaf(v11, v11, sumB));
                uint32_t hA, lA, hB, lB;
                split2(v00, v01, hA, lA);
                split2(v10, v11, hB, lB);
                int d = nt * 8 + qc;
                *(uint32_t*)(oh + offA + d) = hA;
                *(uint32_t*)(ol + offA + d) = lA;
                *(uint32_t*)(oh + offB + d) = hB;
                *(uint32_t*)(ol + offB + d) = lB;
            }
            sumA += __shfl_xor_sync(0xffffffffu, sumA, 1);
            sumA += __shfl_xor_sync(0xffffffffu, sumA, 2);
            sumB += __shfl_xor_sync(0xffffffffu, sumB, 1);
            sumB += __shfl_xor_sync(0xffffffffu, sumB, 2);
            if ((lane & 3) == 0) {
                float* dst = sel ? g_sk : g_sq;
                dst[(size_t)mhA * S_LEN + sA] = sumA;
                dst[(size_t)mhB * S_LEN + sB] = sumB;
            }
        }
    }
}

// ---------------- K3: attention (HMMA, cp.async pipelined) ----------------
// smem: Qhi 0(16K), Qlo 16K, stages@32K: 2 x {Khi 8K, Klo 8K, Vh 8K, Vl 8K, sk 256},
// P fp16 [128][64] @98816 (16K). Total 115200 B -> 2 CTAs/SM.
#define A_QHI 0
#define A_QLO 16384
#define A_STG 32768
#define STG_SZ 33024
#define ST_KHI 0
#define ST_KLO 8192
#define ST_VH  16384
#define ST_VL  24576
#define ST_SK  32768
#define A_P    (A_STG + 2 * STG_SZ)
#define ASMEM  (A_P + 16384)

__global__ __launch_bounds__(256, 2) void attn_hmma(float* __restrict__ ctx_out,
                                                    float* __restrict__ score_out)
{
    extern __shared__ char sm[];
    const uint32_t sb = smem_u32(sm);
    const int tid = threadIdx.x, wid = tid >> 5, lane = tid & 31;
    const int m = blockIdx.y, q0 = blockIdx.x * 128;
    const int wm = wid >> 1, wn = wid & 1;
    const int lr16 = lane & 15, lk8 = (lane >> 4) << 3;
    const int qr = lane >> 2, qc = (lane & 3) * 2;

    // load Q hi/lo tiles (once)
    #pragma unroll
    for (int g = 0; g < 2; ++g) {
        const __nv_bfloat16* base = g ? g_Qlo : g_Qhi;
        char* dst = sm + (g ? A_QLO : A_QHI);
        #pragma unroll
        for (int i = 0; i < 4; ++i) {
            int u = tid + i * 256;
            int row = u >> 3, c16 = u & 7;
            uint4 v = *((const uint4*)(base + ((size_t)m * S_LEN + q0 + row) * DHEAD) + c16);
            uint32_t byte = row * 128 + c16 * 16;
            *(uint4*)(dst + SWZ(byte)) = v;
        }
    }

    // prefetch stage 0
    {
        const uint32_t stg = sb + A_STG;
        #pragma unroll
        for (int i = 0; i < 2; ++i) {
            int u = tid + i * 256;
            int row = u >> 3, c16 = u & 7;
            uint32_t so = SWZ((uint32_t)(row * 128 + c16 * 16));
            size_t goff = ((size_t)m * S_LEN + row) * DHEAD + c16 * 8;
            CP16(stg + ST_KHI + so, (const char*)(g_Khi + goff));
            CP16(stg + ST_KLO + so, (const char*)(g_Klo + goff));
            CP16(stg + ST_VH  + so, (const char*)(g_Vh + goff));
            CP16(stg + ST_VL  + so, (const char*)(g_Vl + goff));
        }
        if (tid < 16) CP16(stg + ST_SK + tid * 16,
                           (const char*)(g_sk + (size_t)m * S_LEN) + tid * 16);
        CP_COMMIT();
    }

    float sqr[2][2];
    #pragma unroll
    for (int mt = 0; mt < 2; ++mt) {
        sqr[mt][0] = g_sq[(size_t)m * S_LEN + q0 + wm * 32 + mt * 16 + qr];
        sqr[mt][1] = g_sq[(size_t)m * S_LEN + q0 + wm * 32 + mt * 16 + qr + 8];
    }

    float ctx[2][4][4];
    #pragma unroll
    for (int mt = 0; mt < 2; ++mt)
        #pragma unroll
        for (int nt = 0; nt < 4; ++nt)
            #pragma unroll
            for (int c = 0; c < 4; ++c) ctx[mt][nt][c] = 0.f;

    for (int t = 0; t < 32; ++t) {
        const int t0 = t * 64;
        const uint32_t stg = sb + A_STG + (uint32_t)(t & 1) * STG_SZ;

        CP_WAIT0();
        __syncthreads();   // stage t ready; prior GEMM2 done (P + other stage free)

        if (t < 31) {      // prefetch stage t+1
            const uint32_t nstg = sb + A_STG + (uint32_t)((t + 1) & 1) * STG_SZ;
            const int n0r = t0 + 64;
            #pragma unroll
            for (int i = 0; i < 2; ++i) {
                int u = tid + i * 256;
                int row = u >> 3, c16 = u & 7;
                uint32_t so = SWZ((uint32_t)(row * 128 + c16 * 16));
                size_t goff = ((size_t)m * S_LEN + n0r + row) * DHEAD + c16 * 8;
                CP16(nstg + ST_KHI + so, (const char*)(g_Khi + goff));
                CP16(nstg + ST_KLO + so, (const char*)(g_Klo + goff));
                CP16(nstg + ST_VH  + so, (const char*)(g_Vh + goff));
                CP16(nstg + ST_VL  + so, (const char*)(g_Vl + goff));
            }
            if (tid < 16) CP16(nstg + ST_SK + tid * 16,
                               (const char*)(g_sk + (size_t)m * S_LEN + n0r) + tid * 16);
            CP_COMMIT();
        }

        // ---- GEMM1: S = Q·K^T (bf16x3) ----
        float sacc[2][4][4];
        #pragma unroll
        for (int mt = 0; mt < 2; ++mt)
            #pragma unroll
            for (int nt = 0; nt < 4; ++nt)
                #pragma unroll
                for (int c = 0; c < 4; ++c) sacc[mt][nt][c] = 0.f;

        #pragma unroll
        for (int ks = 0; ks < 4; ++ks) {
            const uint32_t kb = (ks * 16 + lk8) * 2;
            uint32_t ahi[2][4], alo[2][4];
            #pragma unroll
            for (int mt = 0; mt < 2; ++mt) {
                uint32_t byte = (wm * 32 + mt * 16 + lr16) * 128 + kb;
                ldsm4(ahi[mt], sb + A_QHI + SWZ(byte));
                ldsm4(alo[mt], sb + A_QLO + SWZ(byte));
            }
            #pragma unroll
            for (int np = 0; np < 2; ++np) {
                uint32_t byte = (wn * 32 + np * 16 + lr16) * 128 + kb;
                uint32_t bh[4], bl[4];
                ldsm4(bh, stg + ST_KHI + SWZ(byte));
                ldsm4(bl, stg + ST_KLO + SWZ(byte));
                #pragma unroll
                for (int h = 0; h < 2; ++h)
                    #pragma unroll
                    for (int mt = 0; mt < 2; ++mt) {
                        float* c = sacc[mt][np * 2 + h];
                        mma_bf16(c, ahi[mt], bh[h], bh[h + 2]);
                        mma_bf16(c, ahi[mt], bl[h], bl[h + 2]);
                        mma_bf16(c, alo[mt], bh[h], bh[h + 2]);
                    }
            }
        }

        // ---- epilogue: scores + exp + P (fp16) to smem ----
        const float* skp = (const float*)(sm + A_STG + (t & 1) * STG_SZ + ST_SK);
        #pragma unroll
        for (int mt = 0; mt < 2; ++mt) {
            const int rl = wm * 32 + mt * 16 + qr;
            float* srowA = score_out + ((size_t)m * S_LEN + q0 + rl) * S_LEN + t0;
            float* srowB = srowA + 8 * S_LEN;
            #pragma unroll
            for (int nt = 0; nt < 4; ++nt) {
                const float* c = sacc[mt][nt];
                const int cg = wn * 32 + nt * 8 + qc;
                float k0v = skp[cg], k1v = skp[cg + 1];
                float s00 = (sqr[mt][0] + k0v - 2.f * c[0]) * -0.0625f;
                float s01 = (sqr[mt][0] + k1v - 2.f * c[1]) * -0.0625f;
                float s10 = (sqr[mt][1] + k0v - 2.f * c[2]) * -0.0625f;
                float s11 = (sqr[mt][1] + k1v - 2.f * c[3]) * -0.0625f;
                *(float2*)(srowA + cg) = make_float2(s00, s01);
                *(float2*)(srowB + cg) = make_float2(s10, s11);
                __half2 pA = __floats2half2_rn(__expf(s00), __expf(s01));
                __half2 pB = __floats2half2_rn(__expf(s10), __expf(s11));
                uint32_t byteA = rl * 128 + cg * 2;
                uint32_t byteB = (rl + 8) * 128 + cg * 2;
                *(uint32_t*)(sm + A_P + SWZ(byteA)) = *reinterpret_cast<uint32_t*>(&pA);
                *(uint32_t*)(sm + A_P + SWZ(byteB)) = *reinterpret_cast<uint32_t*>(&pB);
            }
        }
        __syncthreads();

        // ---- GEMM2: ctx += P·V (fp16, V hi/lo via ldmatrix.trans) ----
        #pragma unroll
        for (int ks = 0; ks < 4; ++ks) {
            const uint32_t kb = (ks * 16 + lk8) * 2;
            uint32_t pf[2][4];
            #pragma unroll
            for (int mt = 0; mt < 2; ++mt) {
                uint32_t byte = (wm * 32 + mt * 16 + lr16) * 128 + kb;
                ldsm4(pf[mt], sb + A_P + SWZ(byte));
            }
            const int kt = ks * 16 + (lane & 7) + lk8;
            #pragma unroll
            for (int np = 0; np < 2; ++np) {
                const int nb = wn * 32 + np * 16 + (lane & 8);
                uint32_t byte = kt * 128 + nb * 2;
                uint32_t vh[4], vl[4];
                ldsm4t(vh, stg + ST_VH + SWZ(byte));
                ldsm4t(vl, stg + ST_VL + SWZ(byte));
                #pragma unroll
                for (int h = 0; h < 2; ++h)
                    #pragma unroll
                    for (int mt = 0; mt < 2; ++mt) {
                        float* c = ctx[mt][np * 2 + h];
                        mma_f16(c, pf[mt], vh[h], vh[h + 2]);
                        mma_f16(c, pf[mt], vl[h], vl[h + 2]);
                    }
            }
        }
    }

    // ---- write ctx ----
    const int bb = m >> 4, hh = m & 15;
    #pragma unroll
    for (int mt = 0; mt < 2; ++mt) {
        const int rl = wm * 32 + mt * 16 + qr;
        #pragma unroll
        for (int nt = 0; nt < 4; ++nt) {
            const float* c = ctx[mt][nt];
            const int d = wn * 32 + nt * 8 + qc;
            float* dA = ctx_out + ((size_t)(q0 + rl) * BATCH + bb) * HID + hh * 64 + d;
            float* dB = ctx_out + ((size_t)(q0 + rl + 8) * BATCH + bb) * HID + hh * 64 + d;
            *(float2*)dA = make_float2(c[0], c[1]);
            *(float2*)dB = make_float2(c[2], c[3]);
        }
    }
}

// ---------------------------------------------------------------------------
extern "C" void kernel_launch(void* const* d_in, const int* in_sizes, int n_in,
                              void* d_out, int out_size)
{
    const float* hidden = (const float*)d_in[0];
    const float* W      = (const float*)d_in[1];
    const float* bias   = (const float*)d_in[2];
    float* ctx_out   = (float*)d_out;
    float* score_out = ctx_out + (size_t)S_LEN * BATCH * HID;

    convert_kernel<<<1024, 256>>>(hidden, M_DIM * K_DIM / 4, 0);
    convert_kernel<<<1024, 256>>>(W,      N_DIM * K_DIM / 4, 1);

    cudaFuncSetAttribute(qkv_hmma, cudaFuncAttributeMaxDynamicSharedMemorySize, QSMEM);
    dim3 g1(N_DIM / 128, M_DIM / 128);
    qkv_hmma<<<g1, 256, QSMEM>>>(bias);

    cudaFuncSetAttribute(attn_hmma, cudaFuncAttributeMaxDynamicSharedMemorySize, ASMEM);
    dim3 g2(S_LEN / 128, MHEADS);
    attn_hmma<<<g2, 256, ASMEM>>>(ctx_out, score_out);
}

// round 6
// speedup vs baseline: 4.8019x; 1.6291x over previous
#include <cuda_runtime.h>
#include <cuda_fp16.h>
#include <cstdint>

#define S_LEN  2048
#define BATCH  2
#define HID    1024
#define DHEAD  64
#define MHEADS 32
#define K_DIM  1024
#define N_DIM  3072
#define M_DIM  4096

// ---------------- scratch (__device__ globals) ----------------
__device__ __half g_hid[(size_t)M_DIM * K_DIM];
__device__ __half g_w  [(size_t)N_DIM * K_DIM];
__device__ __half g_Q  [(size_t)MHEADS * S_LEN * DHEAD];
__device__ __half g_K  [(size_t)MHEADS * S_LEN * DHEAD];
__device__ __half g_V  [(size_t)MHEADS * S_LEN * DHEAD];
__device__ float  g_sq [(size_t)MHEADS * S_LEN];
__device__ float  g_sk [(size_t)MHEADS * S_LEN];

// ---------------- helpers ----------------
#define SWZ(o) ((o) ^ (((o) >> 3) & 0x70))

__device__ __forceinline__ uint32_t smem_u32(const void* p) {
    uint32_t a;
    asm("{ .reg .u64 t; cvta.to.shared.u64 t, %1; cvt.u32.u64 %0, t; }" : "=r"(a) : "l"(p));
    return a;
}
__device__ __forceinline__ void ldsm4(uint32_t r[4], uint32_t a) {
    asm volatile("ldmatrix.sync.aligned.m8n8.x4.shared.b16 {%0,%1,%2,%3}, [%4];"
        : "=r"(r[0]), "=r"(r[1]), "=r"(r[2]), "=r"(r[3]) : "r"(a));
}
__device__ __forceinline__ void ldsm4t(uint32_t r[4], uint32_t a) {
    asm volatile("ldmatrix.sync.aligned.m8n8.x4.trans.shared.b16 {%0,%1,%2,%3}, [%4];"
        : "=r"(r[0]), "=r"(r[1]), "=r"(r[2]), "=r"(r[3]) : "r"(a));
}
__device__ __forceinline__ void mma_f16(float c[4], const uint32_t a[4],
                                        uint32_t b0, uint32_t b1) {
    asm volatile("mma.sync.aligned.m16n8k16.row.col.f32.f16.f16.f32 "
        "{%0,%1,%2,%3}, {%4,%5,%6,%7}, {%8,%9}, {%0,%1,%2,%3};"
        : "+f"(c[0]), "+f"(c[1]), "+f"(c[2]), "+f"(c[3])
        : "r"(a[0]), "r"(a[1]), "r"(a[2]), "r"(a[3]), "r"(b0), "r"(b1));
}
__device__ __forceinline__ uint32_t pack_h2(float x, float y) {
    __half2 h = __floats2half2_rn(x, y);
    return *reinterpret_cast<uint32_t*>(&h);
}
#define CP16(dst, src) asm volatile("cp.async.cg.shared.global [%0], [%1], 16;" :: "r"(dst), "l"(src))
#define CP_COMMIT()    asm volatile("cp.async.commit_group;" ::: "memory")
#define CP_WAIT0()     asm volatile("cp.async.wait_group 0;" ::: "memory")

// ---------------- K1: fp32 -> fp16 ----------------
__global__ __launch_bounds__(256) void convert_kernel(const float* __restrict__ src,
                                                      int n4, int which)
{
    __half* dst = which ? g_w : g_hid;
    for (int i = blockIdx.x * blockDim.x + threadIdx.x; i < n4;
         i += gridDim.x * blockDim.x) {
        float4 v = ((const float4*)src)[i];
        ((uint2*)dst)[i] = make_uint2(pack_h2(v.x, v.y), pack_h2(v.z, v.w));
    }
}

// ---------------- K2: QKV GEMM (fp16 HMMA, cp.async double-buffered) -------
#define QST_A 0
#define QST_B 16384
#define QSTG  32768
#define QSMEM 65536

__global__ __launch_bounds__(256, 2) void qkv_hmma(const float* __restrict__ bias)
{
    extern __shared__ char sm[];
    const uint32_t sb = smem_u32(sm);
    const int tid = threadIdx.x, wid = tid >> 5, lane = tid & 31;
    const int n0 = blockIdx.x * 128, m0 = blockIdx.y * 128;
    const int wm = wid >> 1, wn = wid & 1;
    const int lr16 = lane & 15, lk8 = (lane >> 4) << 3;
    const int qr = lane >> 2, qc = (lane & 3) * 2;

    float acc[2][8][4];
    #pragma unroll
    for (int mt = 0; mt < 2; ++mt)
        #pragma unroll
        for (int nt = 0; nt < 8; ++nt)
            #pragma unroll
            for (int c = 0; c < 4; ++c) acc[mt][nt][c] = 0.f;

    // prefetch stage 0
    {
        const uint32_t stg = sb;
        #pragma unroll
        for (int i = 0; i < 4; ++i) {
            int u = tid + i * 256;
            int row = u >> 3, c16 = u & 7;
            uint32_t so = SWZ((uint32_t)(row * 128 + c16 * 16));
            CP16(stg + QST_A + so, (const char*)(g_hid + (size_t)(m0 + row) * K_DIM + c16 * 8));
            CP16(stg + QST_B + so, (const char*)(g_w   + (size_t)(n0 + row) * K_DIM + c16 * 8));
        }
        CP_COMMIT();
    }

    for (int kc = 0; kc < 16; ++kc) {
        const uint32_t stg = sb + (uint32_t)(kc & 1) * QSTG;
        CP_WAIT0();
        __syncthreads();

        if (kc < 15) {
            const uint32_t nstg = sb + (uint32_t)((kc + 1) & 1) * QSTG;
            const int k0 = (kc + 1) * 64;
            #pragma unroll
            for (int i = 0; i < 4; ++i) {
                int u = tid + i * 256;
                int row = u >> 3, c16 = u & 7;
                uint32_t so = SWZ((uint32_t)(row * 128 + c16 * 16));
                CP16(nstg + QST_A + so, (const char*)(g_hid + (size_t)(m0 + row) * K_DIM + k0 + c16 * 8));
                CP16(nstg + QST_B + so, (const char*)(g_w   + (size_t)(n0 + row) * K_DIM + k0 + c16 * 8));
            }
            CP_COMMIT();
        }

        #pragma unroll
        for (int ks = 0; ks < 4; ++ks) {
            const uint32_t kb = (ks * 16 + lk8) * 2;
            uint32_t a[2][4];
            #pragma unroll
            for (int mt = 0; mt < 2; ++mt) {
                uint32_t byte = (wm * 32 + mt * 16 + lr16) * 128 + kb;
                ldsm4(a[mt], stg + QST_A + SWZ(byte));
            }
            #pragma unroll
            for (int np = 0; np < 4; ++np) {
                uint32_t byte = (wn * 64 + np * 16 + lr16) * 128 + kb;
                uint32_t b[4];
                ldsm4(b, stg + QST_B + SWZ(byte));
                #pragma unroll
                for (int h = 0; h < 2; ++h)
                    #pragma unroll
                    for (int mt = 0; mt < 2; ++mt)
                        mma_f16(acc[mt][np * 2 + h], a[mt], b[h], b[h + 2]);
            }
        }
    }

    // epilogue
    const int nbase = n0 + wn * 64;
    const int head = nbase / 192;
    const int wsel = nbase - head * 192;
    const int sel = wsel >> 6;

    #pragma unroll
    for (int mt = 0; mt < 2; ++mt) {
        const int rA = m0 + wm * 32 + mt * 16 + qr;
        const int rB = rA + 8;
        const int sA = rA >> 1, mhA = (rA & 1) * 16 + head;
        const int sB = rB >> 1, mhB = (rB & 1) * 16 + head;
        const size_t offA = ((size_t)mhA * S_LEN + sA) * DHEAD;
        const size_t offB = ((size_t)mhB * S_LEN + sB) * DHEAD;
        if (sel == 2) {
            #pragma unroll
            for (int nt = 0; nt < 8; ++nt) {
                const float* c = acc[mt][nt];
                const int n = nbase + nt * 8 + qc;
                float b0 = __ldg(bias + n), b1 = __ldg(bias + n + 1);
                int d = nt * 8 + qc;
                *(uint32_t*)(g_V + offA + d) = pack_h2(c[0] + b0, c[1] + b1);
                *(uint32_t*)(g_V + offB + d) = pack_h2(c[2] + b0, c[3] + b1);
            }
        } else {
            __half* oh = sel ? g_K : g_Q;
            float sumA = 0.f, sumB = 0.f;
            #pragma unroll
            for (int nt = 0; nt < 8; ++nt) {
                const float* c = acc[mt][nt];
                const int n = nbase + nt * 8 + qc;
                float b0 = __ldg(bias + n), b1 = __ldg(bias + n + 1);
                float v00 = c[0] + b0, v01 = c[1] + b1;
                float v10 = c[2] + b0, v11 = c[3] + b1;
                sumA = fmaf(v00, v00, fmaf(v01, v01, sumA));
                sumB = fmaf(v10, v10, fmaf(v11, v11, sumB));
                int d = nt * 8 + qc;
                *(uint32_t*)(oh + offA + d) = pack_h2(v00, v01);
                *(uint32_t*)(oh + offB + d) = pack_h2(v10, v11);
            }
            sumA += __shfl_xor_sync(0xffffffffu, sumA, 1);
            sumA += __shfl_xor_sync(0xffffffffu, sumA, 2);
            sumB += __shfl_xor_sync(0xffffffffu, sumB, 1);
            sumB += __shfl_xor_sync(0xffffffffu, sumB, 2);
            if ((lane & 3) == 0) {
                float* dst = sel ? g_sk : g_sq;
                dst[(size_t)mhA * S_LEN + sA] = sumA;
                dst[(size_t)mhB * S_LEN + sB] = sumB;
            }
        }
    }
}

// ---------------- K3: attention (fp16 HMMA, cp.async pipelined) ------------
// smem: Q 0(16K), stages@16K: 2 x {K 8K, V 8K, sk 256}, P fp16 @49664 (16K).
// Total 66048 B -> 3 CTAs/SM.
#define A_Q   0
#define A_STG 16384
#define STG_SZ 16640
#define ST_K  0
#define ST_V  8192
#define ST_SK 16384
#define A_P   (A_STG + 2 * STG_SZ)
#define ASMEM (A_P + 16384)

__global__ __launch_bounds__(256, 3) void attn_hmma(float* __restrict__ ctx_out,
                                                    float* __restrict__ score_out)
{
    extern __shared__ char sm[];
    const uint32_t sb = smem_u32(sm);
    const int tid = threadIdx.x, wid = tid >> 5, lane = tid & 31;
    const int m = blockIdx.y, q0 = blockIdx.x * 128;
    const int wm = wid >> 1, wn = wid & 1;
    const int lr16 = lane & 15, lk8 = (lane >> 4) << 3;
    const int qr = lane >> 2, qc = (lane & 3) * 2;

    // load Q tile (once) via cp.async
    #pragma unroll
    for (int i = 0; i < 4; ++i) {
        int u = tid + i * 256;
        int row = u >> 3, c16 = u & 7;
        uint32_t so = SWZ((uint32_t)(row * 128 + c16 * 16));
        CP16(sb + A_Q + so, (const char*)(g_Q + ((size_t)m * S_LEN + q0 + row) * DHEAD + c16 * 8));
    }
    // prefetch stage 0
    {
        const uint32_t stg = sb + A_STG;
        #pragma unroll
        for (int i = 0; i < 2; ++i) {
            int u = tid + i * 256;
            int row = u >> 3, c16 = u & 7;
            uint32_t so = SWZ((uint32_t)(row * 128 + c16 * 16));
            size_t goff = ((size_t)m * S_LEN + row) * DHEAD + c16 * 8;
            CP16(stg + ST_K + so, (const char*)(g_K + goff));
            CP16(stg + ST_V + so, (const char*)(g_V + goff));
        }
        if (tid < 16) CP16(stg + ST_SK + tid * 16,
                           (const char*)(g_sk + (size_t)m * S_LEN) + tid * 16);
        CP_COMMIT();
    }

    float sqr[2][2];
    #pragma unroll
    for (int mt = 0; mt < 2; ++mt) {
        sqr[mt][0] = g_sq[(size_t)m * S_LEN + q0 + wm * 32 + mt * 16 + qr];
        sqr[mt][1] = g_sq[(size_t)m * S_LEN + q0 + wm * 32 + mt * 16 + qr + 8];
    }

    float ctx[2][4][4];
    #pragma unroll
    for (int mt = 0; mt < 2; ++mt)
        #pragma unroll
        for (int nt = 0; nt < 4; ++nt)
            #pragma unroll
            for (int c = 0; c < 4; ++c) ctx[mt][nt][c] = 0.f;

    for (int t = 0; t < 32; ++t) {
        const int t0 = t * 64;
        const uint32_t stg = sb + A_STG + (uint32_t)(t & 1) * STG_SZ;

        CP_WAIT0();
        __syncthreads();   // stage t (and Q on t=0) ready; prior GEMM2 done

        if (t < 31) {      // prefetch stage t+1
            const uint32_t nstg = sb + A_STG + (uint32_t)((t + 1) & 1) * STG_SZ;
            const int n0r = t0 + 64;
            #pragma unroll
            for (int i = 0; i < 2; ++i) {
                int u = tid + i * 256;
                int row = u >> 3, c16 = u & 7;
                uint32_t so = SWZ((uint32_t)(row * 128 + c16 * 16));
                size_t goff = ((size_t)m * S_LEN + n0r + row) * DHEAD + c16 * 8;
                CP16(nstg + ST_K + so, (const char*)(g_K + goff));
                CP16(nstg + ST_V + so, (const char*)(g_V + goff));
            }
            if (tid < 16) CP16(nstg + ST_SK + tid * 16,
                               (const char*)(g_sk + (size_t)m * S_LEN + n0r) + tid * 16);
            CP_COMMIT();
        }

        // ---- GEMM1: S = Q·K^T (fp16) ----
        float sacc[2][4][4];
        #pragma unroll
        for (int mt = 0; mt < 2; ++mt)
            #pragma unroll
            for (int nt = 0; nt < 4; ++nt)
                #pragma unroll
                for (int c = 0; c < 4; ++c) sacc[mt][nt][c] = 0.f;

        #pragma unroll
        for (int ks = 0; ks < 4; ++ks) {
            const uint32_t kb = (ks * 16 + lk8) * 2;
            uint32_t a[2][4];
            #pragma unroll
            for (int mt = 0; mt < 2; ++mt) {
                uint32_t byte = (wm * 32 + mt * 16 + lr16) * 128 + kb;
                ldsm4(a[mt], sb + A_Q + SWZ(byte));
            }
            #pragma unroll
            for (int np = 0; np < 2; ++np) {
                uint32_t byte = (wn * 32 + np * 16 + lr16) * 128 + kb;
                uint32_t b[4];
                ldsm4(b, stg + ST_K + SWZ(byte));
                #pragma unroll
                for (int h = 0; h < 2; ++h)
                    #pragma unroll
                    for (int mt = 0; mt < 2; ++mt)
                        mma_f16(sacc[mt][np * 2 + h], a[mt], b[h], b[h + 2]);
            }
        }

        // ---- epilogue: scores + exp + P (fp16) to smem ----
        const float* skp = (const float*)(sm + A_STG + (t & 1) * STG_SZ + ST_SK);
        #pragma unroll
        for (int mt = 0; mt < 2; ++mt) {
            const int rl = wm * 32 + mt * 16 + qr;
            float* srowA = score_out + ((size_t)m * S_LEN + q0 + rl) * S_LEN + t0;
            float* srowB = srowA + 8 * S_LEN;
            #pragma unroll
            for (int nt = 0; nt < 4; ++nt) {
                const float* c = sacc[mt][nt];
                const int cg = wn * 32 + nt * 8 + qc;
                float k0v = skp[cg], k1v = skp[cg + 1];
                float s00 = (sqr[mt][0] + k0v - 2.f * c[0]) * -0.0625f;
                float s01 = (sqr[mt][0] + k1v - 2.f * c[1]) * -0.0625f;
                float s10 = (sqr[mt][1] + k0v - 2.f * c[2]) * -0.0625f;
                float s11 = (sqr[mt][1] + k1v - 2.f * c[3]) * -0.0625f;
                *(float2*)(srowA + cg) = make_float2(s00, s01);
                *(float2*)(srowB + cg) = make_float2(s10, s11);
                uint32_t byteA = rl * 128 + cg * 2;
                uint32_t byteB = (rl + 8) * 128 + cg * 2;
                *(uint32_t*)(sm + A_P + SWZ(byteA)) = pack_h2(__expf(s00), __expf(s01));
                *(uint32_t*)(sm + A_P + SWZ(byteB)) = pack_h2(__expf(s10), __expf(s11));
            }
        }
        __syncthreads();

        // ---- GEMM2: ctx += P·V (fp16, V via ldmatrix.trans) ----
        #pragma unroll
        for (int ks = 0; ks < 4; ++ks) {
            const uint32_t kb = (ks * 16 + lk8) * 2;
            uint32_t pf[2][4];
            #pragma unroll
            for (int mt = 0; mt < 2; ++mt) {
                uint32_t byte = (wm * 32 + mt * 16 + lr16) * 128 + kb;
                ldsm4(pf[mt], sb + A_P + SWZ(byte));
            }
            const int kt = ks * 16 + (lane & 7) + lk8;
            #pragma unroll
            for (int np = 0; np < 2; ++np) {
                const int nb = wn * 32 + np * 16 + (lane & 8);
                uint32_t byte = kt * 128 + nb * 2;
                uint32_t vh[4];
                ldsm4t(vh, stg + ST_V + SWZ(byte));
                #pragma unroll
                for (int h = 0; h < 2; ++h)
                    #pragma unroll
                    for (int mt = 0; mt < 2; ++mt)
                        mma_f16(ctx[mt][np * 2 + h], pf[mt], vh[h], vh[h + 2]);
            }
        }
    }

    // ---- write ctx ----
    const int bb = m >> 4, hh = m & 15;
    #pragma unroll
    for (int mt = 0; mt < 2; ++mt) {
        const int rl = wm * 32 + mt * 16 + qr;
        #pragma unroll
        for (int nt = 0; nt < 4; ++nt) {
            const float* c = ctx[mt][nt];
            const int d = wn * 32 + nt * 8 + qc;
            float* dA = ctx_out + ((size_t)(q0 + rl) * BATCH + bb) * HID + hh * 64 + d;
            float* dB = ctx_out + ((size_t)(q0 + rl + 8) * BATCH + bb) * HID + hh * 64 + d;
            *(float2*)dA = make_float2(c[0], c[1]);
            *(float2*)dB = make_float2(c[2], c[3]);
        }
    }
}

// ---------------------------------------------------------------------------
extern "C" void kernel_launch(void* const* d_in, const int* in_sizes, int n_in,
                              void* d_out, int out_size)
{
    const float* hidden = (const float*)d_in[0];
    const float* W      = (const float*)d_in[1];
    const float* bias   = (const float*)d_in[2];
    float* ctx_out   = (float*)d_out;
    float* score_out = ctx_out + (size_t)S_LEN * BATCH * HID;

    convert_kernel<<<1024, 256>>>(hidden, M_DIM * K_DIM / 4, 0);
    convert_kernel<<<1024, 256>>>(W,      N_DIM * K_DIM / 4, 1);

    cudaFuncSetAttribute(qkv_hmma, cudaFuncAttributeMaxDynamicSharedMemorySize, QSMEM);
    dim3 g1(N_DIM / 128, M_DIM / 128);
    qkv_hmma<<<g1, 256, QSMEM>>>(bias);

    cudaFuncSetAttribute(attn_hmma, cudaFuncAttributeMaxDynamicSharedMemorySize, ASMEM);
    dim3 g2(S_LEN / 128, MHEADS);
    attn_hmma<<<g2, 256, ASMEM>>>(ctx_out, score_out);
}

// round 7
// speedup vs baseline: 6.6270x; 1.3801x over previous
#include <cuda_runtime.h>
#include <cuda_fp16.h>
#include <cstdint>

#define S_LEN  2048
#define BATCH  2
#define HID    1024
#define DHEAD  64
#define MHEADS 32
#define K_DIM  1024
#define N_DIM  3072
#define M_DIM  4096

// ---------------- scratch (__device__ globals) ----------------
__device__ __half g_hid[(size_t)M_DIM * K_DIM];
__device__ __half g_w  [(size_t)N_DIM * K_DIM];
__device__ __half g_Q  [(size_t)MHEADS * S_LEN * DHEAD];
__device__ __half g_K  [(size_t)MHEADS * S_LEN * DHEAD];
__device__ __half g_V  [(size_t)MHEADS * S_LEN * DHEAD];
__device__ float  g_sq [(size_t)MHEADS * S_LEN];
__device__ float  g_sk [(size_t)MHEADS * S_LEN];

// ---------------- helpers ----------------
#define SWZ(o) ((o) ^ (((o) >> 3) & 0x70))

__device__ __forceinline__ uint32_t smem_u32(const void* p) {
    uint32_t a;
    asm("{ .reg .u64 t; cvta.to.shared.u64 t, %1; cvt.u32.u64 %0, t; }" : "=r"(a) : "l"(p));
    return a;
}
__device__ __forceinline__ void ldsm4(uint32_t r[4], uint32_t a) {
    asm volatile("ldmatrix.sync.aligned.m8n8.x4.shared.b16 {%0,%1,%2,%3}, [%4];"
        : "=r"(r[0]), "=r"(r[1]), "=r"(r[2]), "=r"(r[3]) : "r"(a));
}
__device__ __forceinline__ void ldsm4t(uint32_t r[4], uint32_t a) {
    asm volatile("ldmatrix.sync.aligned.m8n8.x4.trans.shared.b16 {%0,%1,%2,%3}, [%4];"
        : "=r"(r[0]), "=r"(r[1]), "=r"(r[2]), "=r"(r[3]) : "r"(a));
}
__device__ __forceinline__ void mma_f16(float c[4], const uint32_t a[4],
                                        uint32_t b0, uint32_t b1) {
    asm volatile("mma.sync.aligned.m16n8k16.row.col.f32.f16.f16.f32 "
        "{%0,%1,%2,%3}, {%4,%5,%6,%7}, {%8,%9}, {%0,%1,%2,%3};"
        : "+f"(c[0]), "+f"(c[1]), "+f"(c[2]), "+f"(c[3])
        : "r"(a[0]), "r"(a[1]), "r"(a[2]), "r"(a[3]), "r"(b0), "r"(b1));
}
__device__ __forceinline__ uint32_t pack_h2(float x, float y) {
    __half2 h = __floats2half2_rn(x, y);
    return *reinterpret_cast<uint32_t*>(&h);
}
#define CP16(dst, src) asm volatile("cp.async.cg.shared.global [%0], [%1], 16;" :: "r"(dst), "l"(src))
#define CP_COMMIT()    asm volatile("cp.async.commit_group;" ::: "memory")
#define CP_WAIT0()     asm volatile("cp.async.wait_group 0;" ::: "memory")

// ---------------- K1: fp32 -> fp16 ----------------
__global__ __launch_bounds__(256) void convert_kernel(const float* __restrict__ src,
                                                      int n4, int which)
{
    __half* dst = which ? g_w : g_hid;
    for (int i = blockIdx.x * blockDim.x + threadIdx.x; i < n4;
         i += gridDim.x * blockDim.x) {
        float4 v = ((const float4*)src)[i];
        ((uint2*)dst)[i] = make_uint2(pack_h2(v.x, v.y), pack_h2(v.z, v.w));
    }
}

// ---------------- K2: QKV GEMM (fp16 HMMA, cp.async double-buffered) -------
#define QST_A 0
#define QST_B 16384
#define QSTG  32768
#define QSMEM 65536

__global__ __launch_bounds__(256, 2) void qkv_hmma(const float* __restrict__ bias)
{
    extern __shared__ char sm[];
    const uint32_t sb = smem_u32(sm);
    const int tid = threadIdx.x, wid = tid >> 5, lane = tid & 31;
    const int n0 = blockIdx.x * 128, m0 = blockIdx.y * 128;
    const int wm = wid >> 1, wn = wid & 1;
    const int lr16 = lane & 15, lk8 = (lane >> 4) << 3;
    const int qr = lane >> 2, qc = (lane & 3) * 2;

    float acc[2][8][4];
    #pragma unroll
    for (int mt = 0; mt < 2; ++mt)
        #pragma unroll
        for (int nt = 0; nt < 8; ++nt)
            #pragma unroll
            for (int c = 0; c < 4; ++c) acc[mt][nt][c] = 0.f;

    {
        const uint32_t stg = sb;
        #pragma unroll
        for (int i = 0; i < 4; ++i) {
            int u = tid + i * 256;
            int row = u >> 3, c16 = u & 7;
            uint32_t so = SWZ((uint32_t)(row * 128 + c16 * 16));
            CP16(stg + QST_A + so, (const char*)(g_hid + (size_t)(m0 + row) * K_DIM + c16 * 8));
            CP16(stg + QST_B + so, (const char*)(g_w   + (size_t)(n0 + row) * K_DIM + c16 * 8));
        }
        CP_COMMIT();
    }

    for (int kc = 0; kc < 16; ++kc) {
        const uint32_t stg = sb + (uint32_t)(kc & 1) * QSTG;
        CP_WAIT0();
        __syncthreads();

        if (kc < 15) {
            const uint32_t nstg = sb + (uint32_t)((kc + 1) & 1) * QSTG;
            const int k0 = (kc + 1) * 64;
            #pragma unroll
            for (int i = 0; i < 4; ++i) {
                int u = tid + i * 256;
                int row = u >> 3, c16 = u & 7;
                uint32_t so = SWZ((uint32_t)(row * 128 + c16 * 16));
                CP16(nstg + QST_A + so, (const char*)(g_hid + (size_t)(m0 + row) * K_DIM + k0 + c16 * 8));
                CP16(nstg + QST_B + so, (const char*)(g_w   + (size_t)(n0 + row) * K_DIM + k0 + c16 * 8));
            }
            CP_COMMIT();
        }

        #pragma unroll
        for (int ks = 0; ks < 4; ++ks) {
            const uint32_t kb = (ks * 16 + lk8) * 2;
            uint32_t a[2][4];
            #pragma unroll
            for (int mt = 0; mt < 2; ++mt) {
                uint32_t byte = (wm * 32 + mt * 16 + lr16) * 128 + kb;
                ldsm4(a[mt], stg + QST_A + SWZ(byte));
            }
            #pragma unroll
            for (int np = 0; np < 4; ++np) {
                uint32_t byte = (wn * 64 + np * 16 + lr16) * 128 + kb;
                uint32_t b[4];
                ldsm4(b, stg + QST_B + SWZ(byte));
                #pragma unroll
                for (int h = 0; h < 2; ++h)
                    #pragma unroll
                    for (int mt = 0; mt < 2; ++mt)
                        mma_f16(acc[mt][np * 2 + h], a[mt], b[h], b[h + 2]);
            }
        }
    }

    // epilogue
    const int nbase = n0 + wn * 64;
    const int head = nbase / 192;
    const int wsel = nbase - head * 192;
    const int sel = wsel >> 6;

    #pragma unroll
    for (int mt = 0; mt < 2; ++mt) {
        const int rA = m0 + wm * 32 + mt * 16 + qr;
        const int rB = rA + 8;
        const int sA = rA >> 1, mhA = (rA & 1) * 16 + head;
        const int sB = rB >> 1, mhB = (rB & 1) * 16 + head;
        const size_t offA = ((size_t)mhA * S_LEN + sA) * DHEAD;
        const size_t offB = ((size_t)mhB * S_LEN + sB) * DHEAD;
        if (sel == 2) {
            #pragma unroll
            for (int nt = 0; nt < 8; ++nt) {
                const float* c = acc[mt][nt];
                const int n = nbase + nt * 8 + qc;
                float b0 = __ldg(bias + n), b1 = __ldg(bias + n + 1);
                int d = nt * 8 + qc;
                *(uint32_t*)(g_V + offA + d) = pack_h2(c[0] + b0, c[1] + b1);
                *(uint32_t*)(g_V + offB + d) = pack_h2(c[2] + b0, c[3] + b1);
            }
        } else {
            __half* oh = sel ? g_K : g_Q;
            float sumA = 0.f, sumB = 0.f;
            #pragma unroll
            for (int nt = 0; nt < 8; ++nt) {
                const float* c = acc[mt][nt];
                const int n = nbase + nt * 8 + qc;
                float b0 = __ldg(bias + n), b1 = __ldg(bias + n + 1);
                float v00 = c[0] + b0, v01 = c[1] + b1;
                float v10 = c[2] + b0, v11 = c[3] + b1;
                sumA = fmaf(v00, v00, fmaf(v01, v01, sumA));
                sumB = fmaf(v10, v10, fmaf(v11, v11, sumB));
                int d = nt * 8 + qc;
                *(uint32_t*)(oh + offA + d) = pack_h2(v00, v01);
                *(uint32_t*)(oh + offB + d) = pack_h2(v10, v11);
            }
            sumA += __shfl_xor_sync(0xffffffffu, sumA, 1);
            sumA += __shfl_xor_sync(0xffffffffu, sumA, 2);
            sumB += __shfl_xor_sync(0xffffffffu, sumB, 1);
            sumB += __shfl_xor_sync(0xffffffffu, sumB, 2);
            if ((lane & 3) == 0) {
                float* dst = sel ? g_sk : g_sq;
                dst[(size_t)mhA * S_LEN + sA] = sumA;
                dst[(size_t)mhB * S_LEN + sB] = sumB;
            }
        }
    }
}

// ---------------- K3: attention (FA2-style register dataflow) --------------
// 8 warps x 16 q-rows. Q frags persistent in regs; P never touches smem.
// smem: Q stage 16K (used once), stages@16K: 2 x {K 8K, V 8K, sk 256}.
#define A_Q   0
#define A_STG 16384
#define STG_SZ 16640
#define ST_K  0
#define ST_V  8192
#define ST_SK 16384
#define ASMEM (A_STG + 2 * STG_SZ)   // 49664

__global__ __launch_bounds__(256, 2) void attn_hmma(float* __restrict__ ctx_out,
                                                    float* __restrict__ score_out)
{
    extern __shared__ char sm[];
    const uint32_t sb = smem_u32(sm);
    const int tid = threadIdx.x, wid = tid >> 5, lane = tid & 31;
    const int m = blockIdx.y, q0 = blockIdx.x * 128;
    const int lr16 = lane & 15, lk8 = (lane >> 4) << 3;
    const int qr = lane >> 2, qc = (lane & 3) * 2;
    const int row0 = wid * 16;          // warp's q-row base within tile

    // stage Q tile + stage 0 of K/V
    #pragma unroll
    for (int i = 0; i < 4; ++i) {
        int u = tid + i * 256;
        int row = u >> 3, c16 = u & 7;
        uint32_t so = SWZ((uint32_t)(row * 128 + c16 * 16));
        CP16(sb + A_Q + so, (const char*)(g_Q + ((size_t)m * S_LEN + q0 + row) * DHEAD + c16 * 8));
    }
    {
        const uint32_t stg = sb + A_STG;
        #pragma unroll
        for (int i = 0; i < 2; ++i) {
            int u = tid + i * 256;
            int row = u >> 3, c16 = u & 7;
            uint32_t so = SWZ((uint32_t)(row * 128 + c16 * 16));
            size_t goff = ((size_t)m * S_LEN + row) * DHEAD + c16 * 8;
            CP16(stg + ST_K + so, (const char*)(g_K + goff));
            CP16(stg + ST_V + so, (const char*)(g_V + goff));
        }
        if (tid < 16) CP16(stg + ST_SK + tid * 16,
                           (const char*)(g_sk + (size_t)m * S_LEN) + tid * 16);
        CP_COMMIT();
    }
    CP_WAIT0();
    __syncthreads();

    // persistent Q fragments (16 rows x 64 k), 4 k16 chunks
    uint32_t qf[4][4];
    #pragma unroll
    for (int ks = 0; ks < 4; ++ks) {
        uint32_t byte = (row0 + lr16) * 128 + (ks * 16 + lk8) * 2;
        ldsm4(qf[ks], sb + A_Q + SWZ(byte));
    }

    const float sq0 = g_sq[(size_t)m * S_LEN + q0 + row0 + qr];
    const float sq1 = g_sq[(size_t)m * S_LEN + q0 + row0 + qr + 8];

    float ctx[8][4];
    #pragma unroll
    for (int nt = 0; nt < 8; ++nt)
        #pragma unroll
        for (int c = 0; c < 4; ++c) ctx[nt][c] = 0.f;

    for (int t = 0; t < 32; ++t) {
        const int t0 = t * 64;
        const uint32_t stg = sb + A_STG + (uint32_t)(t & 1) * STG_SZ;

        if (t > 0) { CP_WAIT0(); __syncthreads(); }

        if (t < 31) {      // prefetch stage t+1
            const uint32_t nstg = sb + A_STG + (uint32_t)((t + 1) & 1) * STG_SZ;
            const int n0r = t0 + 64;
            #pragma unroll
            for (int i = 0; i < 2; ++i) {
                int u = tid + i * 256;
                int row = u >> 3, c16 = u & 7;
                uint32_t so = SWZ((uint32_t)(row * 128 + c16 * 16));
                size_t goff = ((size_t)m * S_LEN + n0r + row) * DHEAD + c16 * 8;
                CP16(nstg + ST_K + so, (const char*)(g_K + goff));
                CP16(nstg + ST_V + so, (const char*)(g_V + goff));
            }
            if (tid < 16) CP16(nstg + ST_SK + tid * 16,
                               (const char*)(g_sk + (size_t)m * S_LEN + n0r) + tid * 16);
            CP_COMMIT();
        }

        // ---- GEMM1: S(16x64) = Q·K^T ----
        float sacc[8][4];
        #pragma unroll
        for (int nt = 0; nt < 8; ++nt)
            #pragma unroll
            for (int c = 0; c < 4; ++c) sacc[nt][c] = 0.f;

        #pragma unroll
        for (int ks = 0; ks < 4; ++ks) {
            const uint32_t kb = (ks * 16 + lk8) * 2;
            #pragma unroll
            for (int nb = 0; nb < 4; ++nb) {
                uint32_t byte = (nb * 16 + lr16) * 128 + kb;
                uint32_t b[4];
                ldsm4(b, stg + ST_K + SWZ(byte));
                #pragma unroll
                for (int h = 0; h < 2; ++h)
                    mma_f16(sacc[nb * 2 + h], qf[ks], b[h], b[h + 2]);
            }
        }

        // ---- scores + exp -> P fragments in registers ----
        const float* skp = (const float*)(sm + A_STG + (t & 1) * STG_SZ + ST_SK);
        uint32_t pa[4][4];   // A-fragments for GEMM2: [k16 chunk][4 regs]
        float* srowA = score_out + ((size_t)m * S_LEN + q0 + row0 + qr) * S_LEN + t0;
        float* srowB = srowA + 8 * S_LEN;
        #pragma unroll
        for (int nt = 0; nt < 8; ++nt) {
            const float* c = sacc[nt];
            const int cg = nt * 8 + qc;
            float k0v = skp[cg], k1v = skp[cg + 1];
            float s00 = (sq0 + k0v - 2.f * c[0]) * -0.0625f;
            float s01 = (sq0 + k1v - 2.f * c[1]) * -0.0625f;
            float s10 = (sq1 + k0v - 2.f * c[2]) * -0.0625f;
            float s11 = (sq1 + k1v - 2.f * c[3]) * -0.0625f;
            *(float2*)(srowA + cg) = make_float2(s00, s01);
            *(float2*)(srowB + cg) = make_float2(s10, s11);
            uint32_t pA = pack_h2(__expf(s00), __expf(s01));
            uint32_t pB = pack_h2(__expf(s10), __expf(s11));
            // nt -> k16 chunk nt/2; halves: even nt = k 0..7 (a0,a1), odd = k 8..15 (a2,a3)
            pa[nt >> 1][(nt & 1) * 2 + 0] = pA;
            pa[nt >> 1][(nt & 1) * 2 + 1] = pB;
        }

        // ---- GEMM2: ctx(16x64) += P·V ----
        #pragma unroll
        for (int kc = 0; kc < 4; ++kc) {
            const int kt = kc * 16 + (lane & 7) + lk8;
            #pragma unroll
            for (int nd = 0; nd < 4; ++nd) {
                const int nb = nd * 16 + (lane & 8);
                uint32_t byte = kt * 128 + nb * 2;
                uint32_t vh[4];
                ldsm4t(vh, stg + ST_V + SWZ(byte));
                #pragma unroll
                for (int h = 0; h < 2; ++h)
                    mma_f16(ctx[nd * 2 + h], pa[kc], vh[h], vh[h + 2]);
            }
        }
    }

    // ---- write ctx ----
    const int bb = m >> 4, hh = m & 15;
    {
        const int rl = row0 + qr;
        float* dA = ctx_out + ((size_t)(q0 + rl) * BATCH + bb) * HID + hh * 64;
        float* dB = ctx_out + ((size_t)(q0 + rl + 8) * BATCH + bb) * HID + hh * 64;
        #pragma unroll
        for (int nt = 0; nt < 8; ++nt) {
            const float* c = ctx[nt];
            const int d = nt * 8 + qc;
            *(float2*)(dA + d) = make_float2(c[0], c[1]);
            *(float2*)(dB + d) = make_float2(c[2], c[3]);
        }
    }
}

// ---------------------------------------------------------------------------
extern "C" void kernel_launch(void* const* d_in, const int* in_sizes, int n_in,
                              void* d_out, int out_size)
{
    const float* hidden = (const float*)d_in[0];
    const float* W      = (const float*)d_in[1];
    const float* bias   = (const float*)d_in[2];
    float* ctx_out   = (float*)d_out;
    float* score_out = ctx_out + (size_t)S_LEN * BATCH * HID;

    convert_kernel<<<1024, 256>>>(hidden, M_DIM * K_DIM / 4, 0);
    convert_kernel<<<1024, 256>>>(W,      N_DIM * K_DIM / 4, 1);

    cudaFuncSetAttribute(qkv_hmma, cudaFuncAttributeMaxDynamicSharedMemorySize, QSMEM);
    dim3 g1(N_DIM / 128, M_DIM / 128);
    qkv_hmma<<<g1, 256, QSMEM>>>(bias);

    cudaFuncSetAttribute(attn_hmma, cudaFuncAttributeMaxDynamicSharedMemorySize, ASMEM);
    dim3 g2(S_LEN / 128, MHEADS);
    attn_hmma<<<g2, 256, ASMEM>>>(ctx_out, score_out);
}

// round 8
// speedup vs baseline: 7.3884x; 1.1149x over previous
#include <cuda_runtime.h>
#include <cuda_fp16.h>
#include <cstdint>

#define S_LEN  2048
#define BATCH  2
#define HID    1024
#define DHEAD  64
#define MHEADS 32
#define K_DIM  1024
#define N_DIM  3072
#define M_DIM  4096

// ---------------- scratch (__device__ globals) ----------------
__device__ __half g_hid[(size_t)M_DIM * K_DIM];
__device__ __half g_w  [(size_t)N_DIM * K_DIM];
__device__ __half g_Q  [(size_t)MHEADS * S_LEN * DHEAD];
__device__ __half g_K  [(size_t)MHEADS * S_LEN * DHEAD];
__device__ __half g_V  [(size_t)MHEADS * S_LEN * DHEAD];
__device__ float  g_sq [(size_t)MHEADS * S_LEN];
__device__ float  g_sk [(size_t)MHEADS * S_LEN];

// ---------------- helpers ----------------
#define SWZ(o) ((o) ^ (((o) >> 3) & 0x70))

__device__ __forceinline__ uint32_t smem_u32(const void* p) {
    uint32_t a;
    asm("{ .reg .u64 t; cvta.to.shared.u64 t, %1; cvt.u32.u64 %0, t; }" : "=r"(a) : "l"(p));
    return a;
}
__device__ __forceinline__ void ldsm4(uint32_t r[4], uint32_t a) {
    asm volatile("ldmatrix.sync.aligned.m8n8.x4.shared.b16 {%0,%1,%2,%3}, [%4];"
        : "=r"(r[0]), "=r"(r[1]), "=r"(r[2]), "=r"(r[3]) : "r"(a));
}
__device__ __forceinline__ void ldsm4t(uint32_t r[4], uint32_t a) {
    asm volatile("ldmatrix.sync.aligned.m8n8.x4.trans.shared.b16 {%0,%1,%2,%3}, [%4];"
        : "=r"(r[0]), "=r"(r[1]), "=r"(r[2]), "=r"(r[3]) : "r"(a));
}
__device__ __forceinline__ void mma_f16(float c[4], const uint32_t a[4],
                                        uint32_t b0, uint32_t b1) {
    asm volatile("mma.sync.aligned.m16n8k16.row.col.f32.f16.f16.f32 "
        "{%0,%1,%2,%3}, {%4,%5,%6,%7}, {%8,%9}, {%0,%1,%2,%3};"
        : "+f"(c[0]), "+f"(c[1]), "+f"(c[2]), "+f"(c[3])
        : "r"(a[0]), "r"(a[1]), "r"(a[2]), "r"(a[3]), "r"(b0), "r"(b1));
}
__device__ __forceinline__ uint32_t pack_h2(float x, float y) {
    __half2 h = __floats2half2_rn(x, y);
    return *reinterpret_cast<uint32_t*>(&h);
}
#define CP16(dst, src) asm volatile("cp.async.cg.shared.global [%0], [%1], 16;" :: "r"(dst), "l"(src))
#define CP_COMMIT()    asm volatile("cp.async.commit_group;" ::: "memory")
#define CP_WAIT0()     asm volatile("cp.async.wait_group 0;" ::: "memory")

// ---------------- K1: fp32 -> fp16 ----------------
__global__ __launch_bounds__(256) void convert_kernel(const float* __restrict__ src,
                                                      int n4, int which)
{
    __half* dst = which ? g_w : g_hid;
    for (int i = blockIdx.x * blockDim.x + threadIdx.x; i < n4;
         i += gridDim.x * blockDim.x) {
        float4 v = ((const float4*)src)[i];
        ((uint2*)dst)[i] = make_uint2(pack_h2(v.x, v.y), pack_h2(v.z, v.w));
    }
}

// ---------------- K2: QKV GEMM (fp16 HMMA, cp.async double-buffered) -------
#define QST_A 0
#define QST_B 16384
#define QSTG  32768
#define QSMEM 65536

__global__ __launch_bounds__(256, 2) void qkv_hmma(const float* __restrict__ bias)
{
    extern __shared__ char sm[];
    const uint32_t sb = smem_u32(sm);
    const int tid = threadIdx.x, wid = tid >> 5, lane = tid & 31;
    const int n0 = blockIdx.x * 128, m0 = blockIdx.y * 128;
    const int wm = wid >> 1, wn = wid & 1;
    const int lr16 = lane & 15, lk8 = (lane >> 4) << 3;
    const int qr = lane >> 2, qc = (lane & 3) * 2;

    float acc[2][8][4];
    #pragma unroll
    for (int mt = 0; mt < 2; ++mt)
        #pragma unroll
        for (int nt = 0; nt < 8; ++nt)
            #pragma unroll
            for (int c = 0; c < 4; ++c) acc[mt][nt][c] = 0.f;

    {
        const uint32_t stg = sb;
        #pragma unroll
        for (int i = 0; i < 4; ++i) {
            int u = tid + i * 256;
            int row = u >> 3, c16 = u & 7;
            uint32_t so = SWZ((uint32_t)(row * 128 + c16 * 16));
            CP16(stg + QST_A + so, (const char*)(g_hid + (size_t)(m0 + row) * K_DIM + c16 * 8));
            CP16(stg + QST_B + so, (const char*)(g_w   + (size_t)(n0 + row) * K_DIM + c16 * 8));
        }
        CP_COMMIT();
    }

    for (int kc = 0; kc < 16; ++kc) {
        const uint32_t stg = sb + (uint32_t)(kc & 1) * QSTG;
        CP_WAIT0();
        __syncthreads();

        if (kc < 15) {
            const uint32_t nstg = sb + (uint32_t)((kc + 1) & 1) * QSTG;
            const int k0 = (kc + 1) * 64;
            #pragma unroll
            for (int i = 0; i < 4; ++i) {
                int u = tid + i * 256;
                int row = u >> 3, c16 = u & 7;
                uint32_t so = SWZ((uint32_t)(row * 128 + c16 * 16));
                CP16(nstg + QST_A + so, (const char*)(g_hid + (size_t)(m0 + row) * K_DIM + k0 + c16 * 8));
                CP16(nstg + QST_B + so, (const char*)(g_w   + (size_t)(n0 + row) * K_DIM + k0 + c16 * 8));
            }
            CP_COMMIT();
        }

        #pragma unroll
        for (int ks = 0; ks < 4; ++ks) {
            const uint32_t kb = (ks * 16 + lk8) * 2;
            uint32_t a[2][4];
            #pragma unroll
            for (int mt = 0; mt < 2; ++mt) {
                uint32_t byte = (wm * 32 + mt * 16 + lr16) * 128 + kb;
                ldsm4(a[mt], stg + QST_A + SWZ(byte));
            }
            #pragma unroll
            for (int np = 0; np < 4; ++np) {
                uint32_t byte = (wn * 64 + np * 16 + lr16) * 128 + kb;
                uint32_t b[4];
                ldsm4(b, stg + QST_B + SWZ(byte));
                #pragma unroll
                for (int h = 0; h < 2; ++h)
                    #pragma unroll
                    for (int mt = 0; mt < 2; ++mt)
                        mma_f16(acc[mt][np * 2 + h], a[mt], b[h], b[h + 2]);
            }
        }
    }

    // epilogue
    const int nbase = n0 + wn * 64;
    const int head = nbase / 192;
    const int wsel = nbase - head * 192;
    const int sel = wsel >> 6;

    #pragma unroll
    for (int mt = 0; mt < 2; ++mt) {
        const int rA = m0 + wm * 32 + mt * 16 + qr;
        const int rB = rA + 8;
        const int sA = rA >> 1, mhA = (rA & 1) * 16 + head;
        const int sB = rB >> 1, mhB = (rB & 1) * 16 + head;
        const size_t offA = ((size_t)mhA * S_LEN + sA) * DHEAD;
        const size_t offB = ((size_t)mhB * S_LEN + sB) * DHEAD;
        if (sel == 2) {
            #pragma unroll
            for (int nt = 0; nt < 8; ++nt) {
                const float* c = acc[mt][nt];
                const int n = nbase + nt * 8 + qc;
                float b0 = __ldg(bias + n), b1 = __ldg(bias + n + 1);
                int d = nt * 8 + qc;
                *(uint32_t*)(g_V + offA + d) = pack_h2(c[0] + b0, c[1] + b1);
                *(uint32_t*)(g_V + offB + d) = pack_h2(c[2] + b0, c[3] + b1);
            }
        } else {
            __half* oh = sel ? g_K : g_Q;
            float sumA = 0.f, sumB = 0.f;
            #pragma unroll
            for (int nt = 0; nt < 8; ++nt) {
                const float* c = acc[mt][nt];
                const int n = nbase + nt * 8 + qc;
                float b0 = __ldg(bias + n), b1 = __ldg(bias + n + 1);
                float v00 = c[0] + b0, v01 = c[1] + b1;
                float v10 = c[2] + b0, v11 = c[3] + b1;
                sumA = fmaf(v00, v00, fmaf(v01, v01, sumA));
                sumB = fmaf(v10, v10, fmaf(v11, v11, sumB));
                int d = nt * 8 + qc;
                *(uint32_t*)(oh + offA + d) = pack_h2(v00, v01);
                *(uint32_t*)(oh + offB + d) = pack_h2(v10, v11);
            }
            sumA += __shfl_xor_sync(0xffffffffu, sumA, 1);
            sumA += __shfl_xor_sync(0xffffffffu, sumA, 2);
            sumB += __shfl_xor_sync(0xffffffffu, sumB, 1);
            sumB += __shfl_xor_sync(0xffffffffu, sumB, 2);
            if ((lane & 3) == 0) {
                float* dst = sel ? g_sk : g_sq;
                dst[(size_t)mhA * S_LEN + sA] = sumA;
                dst[(size_t)mhB * S_LEN + sB] = sumB;
            }
        }
    }
}

// ---------------- K3: attention (FA2 regs, 4 warps x 32 rows) --------------
// Each K/V fragment load feeds TWO 16-row MMA groups -> half the ldmatrix
// traffic per unit work vs 8x16. Block = 128 threads.
#define A_Q   0
#define A_STG 16384
#define STG_SZ 16640
#define ST_K  0
#define ST_V  8192
#define ST_SK 16384
#define ASMEM (A_STG + 2 * STG_SZ)   // 49664

__global__ __launch_bounds__(128, 2) void attn_hmma(float* __restrict__ ctx_out,
                                                    float* __restrict__ score_out)
{
    extern __shared__ char sm[];
    const uint32_t sb = smem_u32(sm);
    const int tid = threadIdx.x, wid = tid >> 5, lane = tid & 31;
    const int m = blockIdx.y, q0 = blockIdx.x * 128;
    const int lr16 = lane & 15, lk8 = (lane >> 4) << 3;
    const int qr = lane >> 2, qc = (lane & 3) * 2;
    const int row0 = wid * 32;          // warp's q-row base (32 rows / warp)

    // stage Q tile (128 rows x 128B) + stage 0 of K/V
    #pragma unroll
    for (int i = 0; i < 8; ++i) {
        int u = tid + i * 128;
        int row = u >> 3, c16 = u & 7;
        uint32_t so = SWZ((uint32_t)(row * 128 + c16 * 16));
        CP16(sb + A_Q + so, (const char*)(g_Q + ((size_t)m * S_LEN + q0 + row) * DHEAD + c16 * 8));
    }
    {
        const uint32_t stg = sb + A_STG;
        #pragma unroll
        for (int i = 0; i < 4; ++i) {
            int u = tid + i * 128;
            int row = u >> 3, c16 = u & 7;
            uint32_t so = SWZ((uint32_t)(row * 128 + c16 * 16));
            size_t goff = ((size_t)m * S_LEN + row) * DHEAD + c16 * 8;
            CP16(stg + ST_K + so, (const char*)(g_K + goff));
            CP16(stg + ST_V + so, (const char*)(g_V + goff));
        }
        if (tid < 16) CP16(stg + ST_SK + tid * 16,
                           (const char*)(g_sk + (size_t)m * S_LEN) + tid * 16);
        CP_COMMIT();
    }
    CP_WAIT0();
    __syncthreads();

    // persistent Q fragments: 2 row-groups x 4 k16 chunks
    uint32_t qf[2][4][4];
    #pragma unroll
    for (int g = 0; g < 2; ++g)
        #pragma unroll
        for (int ks = 0; ks < 4; ++ks) {
            uint32_t byte = (row0 + g * 16 + lr16) * 128 + (ks * 16 + lk8) * 2;
            ldsm4(qf[g][ks], sb + A_Q + SWZ(byte));
        }

    float sqv[2][2];
    #pragma unroll
    for (int g = 0; g < 2; ++g) {
        sqv[g][0] = g_sq[(size_t)m * S_LEN + q0 + row0 + g * 16 + qr];
        sqv[g][1] = g_sq[(size_t)m * S_LEN + q0 + row0 + g * 16 + qr + 8];
    }

    float ctx[2][8][4];
    #pragma unroll
    for (int g = 0; g < 2; ++g)
        #pragma unroll
        for (int nt = 0; nt < 8; ++nt)
            #pragma unroll
            for (int c = 0; c < 4; ++c) ctx[g][nt][c] = 0.f;

    for (int t = 0; t < 32; ++t) {
        const int t0 = t * 64;
        const uint32_t stg = sb + A_STG + (uint32_t)(t & 1) * STG_SZ;

        if (t > 0) { CP_WAIT0(); __syncthreads(); }

        if (t < 31) {      // prefetch stage t+1
            const uint32_t nstg = sb + A_STG + (uint32_t)((t + 1) & 1) * STG_SZ;
            const int n0r = t0 + 64;
            #pragma unroll
            for (int i = 0; i < 4; ++i) {
                int u = tid + i * 128;
                int row = u >> 3, c16 = u & 7;
                uint32_t so = SWZ((uint32_t)(row * 128 + c16 * 16));
                size_t goff = ((size_t)m * S_LEN + n0r + row) * DHEAD + c16 * 8;
                CP16(nstg + ST_K + so, (const char*)(g_K + goff));
                CP16(nstg + ST_V + so, (const char*)(g_V + goff));
            }
            if (tid < 16) CP16(nstg + ST_SK + tid * 16,
                               (const char*)(g_sk + (size_t)m * S_LEN + n0r) + tid * 16);
            CP_COMMIT();
        }

        // ---- GEMM1: S(32x64) = Q·K^T — each K frag feeds both row groups ----
        float sacc[2][8][4];
        #pragma unroll
        for (int g = 0; g < 2; ++g)
            #pragma unroll
            for (int nt = 0; nt < 8; ++nt)
                #pragma unroll
                for (int c = 0; c < 4; ++c) sacc[g][nt][c] = 0.f;

        #pragma unroll
        for (int ks = 0; ks < 4; ++ks) {
            const uint32_t kb = (ks * 16 + lk8) * 2;
            #pragma unroll
            for (int nb = 0; nb < 4; ++nb) {
                uint32_t byte = (nb * 16 + lr16) * 128 + kb;
                uint32_t b[4];
                ldsm4(b, stg + ST_K + SWZ(byte));
                #pragma unroll
                for (int h = 0; h < 2; ++h)
                    #pragma unroll
                    for (int g = 0; g < 2; ++g)
                        mma_f16(sacc[g][nb * 2 + h], qf[g][ks], b[h], b[h + 2]);
            }
        }

        // ---- scores + exp -> P fragments in registers ----
        const float* skp = (const float*)(sm + A_STG + (t & 1) * STG_SZ + ST_SK);
        uint32_t pa[2][4][4];
        #pragma unroll
        for (int g = 0; g < 2; ++g) {
            float* srowA = score_out + ((size_t)m * S_LEN + q0 + row0 + g * 16 + qr) * S_LEN + t0;
            float* srowB = srowA + 8 * S_LEN;
            #pragma unroll
            for (int nt = 0; nt < 8; ++nt) {
                const float* c = sacc[g][nt];
                const int cg = nt * 8 + qc;
                float2 kv = *(const float2*)(skp + cg);
                float s00 = (sqv[g][0] + kv.x - 2.f * c[0]) * -0.0625f;
                float s01 = (sqv[g][0] + kv.y - 2.f * c[1]) * -0.0625f;
                float s10 = (sqv[g][1] + kv.x - 2.f * c[2]) * -0.0625f;
                float s11 = (sqv[g][1] + kv.y - 2.f * c[3]) * -0.0625f;
                *(float2*)(srowA + cg) = make_float2(s00, s01);
                *(float2*)(srowB + cg) = make_float2(s10, s11);
                pa[g][nt >> 1][(nt & 1) * 2 + 0] = pack_h2(__expf(s00), __expf(s01));
                pa[g][nt >> 1][(nt & 1) * 2 + 1] = pack_h2(__expf(s10), __expf(s11));
            }
        }

        // ---- GEMM2: ctx(32x64) += P·V — each V frag feeds both row groups ----
        #pragma unroll
        for (int kc = 0; kc < 4; ++kc) {
            const int kt = kc * 16 + (lane & 7) + lk8;
            #pragma unroll
            for (int nd = 0; nd < 4; ++nd) {
                const int nb = nd * 16 + (lane & 8);
                uint32_t byte = kt * 128 + nb * 2;
                uint32_t vh[4];
                ldsm4t(vh, stg + ST_V + SWZ(byte));
                #pragma unroll
                for (int h = 0; h < 2; ++h)
                    #pragma unroll
                    for (int g = 0; g < 2; ++g)
                        mma_f16(ctx[g][nd * 2 + h], pa[g][kc], vh[h], vh[h + 2]);
            }
        }
    }

    // ---- write ctx ----
    const int bb = m >> 4, hh = m & 15;
    #pragma unroll
    for (int g = 0; g < 2; ++g) {
        const int rl = row0 + g * 16 + qr;
        float* dA = ctx_out + ((size_t)(q0 + rl) * BATCH + bb) * HID + hh * 64;
        float* dB = ctx_out + ((size_t)(q0 + rl + 8) * BATCH + bb) * HID + hh * 64;
        #pragma unroll
        for (int nt = 0; nt < 8; ++nt) {
            const float* c = ctx[g][nt];
            const int d = nt * 8 + qc;
            *(float2*)(dA + d) = make_float2(c[0], c[1]);
            *(float2*)(dB + d) = make_float2(c[2], c[3]);
        }
    }
}

// ---------------------------------------------------------------------------
extern "C" void kernel_launch(void* const* d_in, const int* in_sizes, int n_in,
                              void* d_out, int out_size)
{
    const float* hidden = (const float*)d_in[0];
    const float* W      = (const float*)d_in[1];
    const float* bias   = (const float*)d_in[2];
    float* ctx_out   = (float*)d_out;
    float* score_out = ctx_out + (size_t)S_LEN * BATCH * HID;

    convert_kernel<<<1024, 256>>>(hidden, M_DIM * K_DIM / 4, 0);
    convert_kernel<<<1024, 256>>>(W,      N_DIM * K_DIM / 4, 1);

    cudaFuncSetAttribute(qkv_hmma, cudaFuncAttributeMaxDynamicSharedMemorySize, QSMEM);
    dim3 g1(N_DIM / 128, M_DIM / 128);
    qkv_hmma<<<g1, 256, QSMEM>>>(bias);

    cudaFuncSetAttribute(attn_hmma, cudaFuncAttributeMaxDynamicSharedMemorySize, ASMEM);
    dim3 g2(S_LEN / 128, MHEADS);
    attn_hmma<<<g2, 128, ASMEM>>>(ctx_out, score_out);
}